// round 2
// baseline (speedup 1.0000x reference)
#include <cuda_runtime.h>

// Problem constants
constexpr int B_ = 4, H_ = 16, N_ = 1024, M_ = 1024, D_ = 64, DIM_ = 1024;
constexpr float SCALE_ = 0.125f;   // 64^-0.5

// Scratch (device globals — no allocation allowed)
__device__ float g_q[(size_t)B_ * H_ * N_ * D_];        // [b,h,n,d]
__device__ float g_k[(size_t)B_ * H_ * M_ * D_];        // [b,h,m,d]
__device__ float g_v[(size_t)B_ * H_ * M_ * D_];        // [b,h,m,d]
__device__ float g_ao[(size_t)B_ * N_ * DIM_];          // [b,n,h*d]
__device__ unsigned g_mbits[(size_t)B_ * N_ * (M_ / 32)]; // packed mask bits

// ---------------------------------------------------------------------------
// Pack int32 mask [b,n,1024] into bitmask words [b,n,32]
// ---------------------------------------------------------------------------
__global__ __launch_bounds__(256) void pack_mask_kernel(const int* __restrict__ mask) {
    int lane = threadIdx.x & 31;
    int row = blockIdx.x * 8 + (threadIdx.x >> 5);   // 0..4095 (b*1024+n)
    const int* mrow = mask + (size_t)row * M_;
    unsigned* brow = g_mbits + (size_t)row * (M_ / 32);
#pragma unroll 4
    for (int w = 0; w < M_ / 32; w++) {
        int v = mrow[w * 32 + lane];
        unsigned bits = __ballot_sync(0xffffffffu, v != 0);
        if (lane == 0) brow[w] = bits;
    }
}

// ---------------------------------------------------------------------------
// Tiled SGEMM: C[M,N] = A[M,K] @ W[K,N] + bias, with scatter epilogues.
// MODE 0: plain row-major store to C (A is read from g_ao)
// MODE 1: Q projection  -> scatter to g_q [b,h,n,d]
// MODE 2: KV projection -> scatter to g_k / g_v [b,h,m,d]
// ---------------------------------------------------------------------------
template <int MODE>
__global__ __launch_bounds__(256) void gemm128_kernel(
    const float* __restrict__ A, const float* __restrict__ W,
    const float* __restrict__ bias, float* __restrict__ C,
    int M, int N, int K)
{
    __shared__ float As[8][128];   // transposed A tile
    __shared__ float Bs[8][128];

    const float* Aeff = (MODE == 0) ? g_ao : A;

    int tid = threadIdx.x;
    int tx = tid & 15, ty = tid >> 4;
    const float* Ab = Aeff + (size_t)blockIdx.y * 128 * K;
    const float* Wb = W + (size_t)blockIdx.x * 128;
    int aRow = tid >> 1, aC = (tid & 1) * 4;
    int bRow = tid >> 5, bC = (tid & 31) * 4;

    float acc[8][8];
#pragma unroll
    for (int i = 0; i < 8; i++)
#pragma unroll
        for (int j = 0; j < 8; j++) acc[i][j] = 0.f;

    for (int k0 = 0; k0 < K; k0 += 8) {
        float4 a4 = *(const float4*)(Ab + (size_t)aRow * K + k0 + aC);
        As[aC + 0][aRow] = a4.x;
        As[aC + 1][aRow] = a4.y;
        As[aC + 2][aRow] = a4.z;
        As[aC + 3][aRow] = a4.w;
        float4 b4 = *(const float4*)(Wb + (size_t)(k0 + bRow) * N + bC);
        *(float4*)&Bs[bRow][bC] = b4;
        __syncthreads();
#pragma unroll
        for (int kk = 0; kk < 8; kk++) {
            float a[8], b[8];
            *(float4*)(a)     = *(const float4*)&As[kk][ty * 8];
            *(float4*)(a + 4) = *(const float4*)&As[kk][ty * 8 + 4];
            *(float4*)(b)     = *(const float4*)&Bs[kk][tx * 8];
            *(float4*)(b + 4) = *(const float4*)&Bs[kk][tx * 8 + 4];
#pragma unroll
            for (int i = 0; i < 8; i++)
#pragma unroll
                for (int j = 0; j < 8; j++)
                    acc[i][j] = fmaf(a[i], b[j], acc[i][j]);
        }
        __syncthreads();
    }

#pragma unroll
    for (int i = 0; i < 8; i++) {
        int gRow = blockIdx.y * 128 + ty * 8 + i;
#pragma unroll
        for (int j = 0; j < 8; j++) {
            int gCol = blockIdx.x * 128 + tx * 8 + j;
            float val = acc[i][j] + bias[gCol];
            if (MODE == 0) {
                C[(size_t)gRow * N + gCol] = val;
            } else if (MODE == 1) {
                int bb = gRow >> 10, n = gRow & 1023;
                int h = gCol >> 6, d = gCol & 63;
                g_q[(((size_t)(bb * H_ + h)) * N_ + n) * D_ + d] = val;
            } else {
                int bb = gRow >> 10, m = gRow & 1023;
                int cc = gCol & 1023;
                int h = cc >> 6, d = cc & 63;
                float* dst = (gCol < DIM_) ? g_k : g_v;
                dst[(((size_t)(bb * H_ + h)) * M_ + m) * D_ + d] = val;
            }
        }
    }
}

// ---------------------------------------------------------------------------
// Fused flash-style masked attention.
// grid (N/128, H, B), 128 threads; 1 thread = 1 query row, online softmax.
// ---------------------------------------------------------------------------
constexpr int QROWS = 128;
constexpr int KTILE = 64;
constexpr int SMEM_ATTN = (QROWS * 65 + KTILE * 65 * 2) * 4; // 66560 B

__global__ __launch_bounds__(128) void attn_kernel() {
    extern __shared__ float sm[];
    float* q_s = sm;                   // [128][65] padded -> conflict-free
    float* k_s = q_s + QROWS * 65;     // [64][65]
    float* v_s = k_s + KTILE * 65;     // [64][65]

    int tid = threadIdx.x;
    int n0 = blockIdx.x * QROWS;
    int h = blockIdx.y, b = blockIdx.z;

    const float* qp = g_q + (((size_t)(b * H_ + h)) * N_ + n0) * D_;
    const float* kp = g_k + ((size_t)(b * H_ + h)) * M_ * D_;
    const float* vp = g_v + ((size_t)(b * H_ + h)) * M_ * D_;
    const unsigned* mbp = g_mbits + ((size_t)(b * N_) + n0) * (M_ / 32);

    // load q tile (pre-scaled by SCALE)
#pragma unroll 4
    for (int i = tid; i < QROWS * 16; i += 128) {
        int r = i >> 4, c = (i & 15) << 2;
        float4 f = *(const float4*)(qp + (size_t)r * D_ + c);
        q_s[r * 65 + c + 0] = f.x * SCALE_;
        q_s[r * 65 + c + 1] = f.y * SCALE_;
        q_s[r * 65 + c + 2] = f.z * SCALE_;
        q_s[r * 65 + c + 3] = f.w * SCALE_;
    }

    float acc[D_];
#pragma unroll
    for (int d = 0; d < D_; d++) acc[d] = 0.f;
    float row_max = -1e30f, row_l = 0.f;
    const int r = tid;

    for (int m0 = 0; m0 < M_; m0 += KTILE) {
        __syncthreads();  // q ready / previous tile fully consumed
#pragma unroll 2
        for (int i = tid; i < KTILE * 16; i += 128) {
            int rr = i >> 4, c = (i & 15) << 2;
            float4 f = *(const float4*)(kp + (size_t)(m0 + rr) * D_ + c);
            k_s[rr * 65 + c + 0] = f.x;
            k_s[rr * 65 + c + 1] = f.y;
            k_s[rr * 65 + c + 2] = f.z;
            k_s[rr * 65 + c + 3] = f.w;
            float4 g = *(const float4*)(vp + (size_t)(m0 + rr) * D_ + c);
            v_s[rr * 65 + c + 0] = g.x;
            v_s[rr * 65 + c + 1] = g.y;
            v_s[rr * 65 + c + 2] = g.z;
            v_s[rr * 65 + c + 3] = g.w;
        }
        __syncthreads();

#pragma unroll
        for (int half = 0; half < 2; half++) {
            const int jb = half * 32;
            unsigned mb = mbp[r * (M_ / 32) + (m0 >> 5) + half];
            float s[32];
#pragma unroll
            for (int j = 0; j < 32; j++) s[j] = 0.f;
#pragma unroll 4
            for (int kk = 0; kk < D_; kk++) {
                float qv = q_s[r * 65 + kk];
#pragma unroll
                for (int j = 0; j < 32; j++)
                    s[j] = fmaf(qv, k_s[(jb + j) * 65 + kk], s[j]);
            }
            float tmax = -1e30f;
#pragma unroll
            for (int j = 0; j < 32; j++) {
                s[j] = ((mb >> j) & 1u) ? s[j] : -1e30f;
                tmax = fmaxf(tmax, s[j]);
            }
            float nm = fmaxf(row_max, tmax);
            float corr = __expf(row_max - nm);
            row_l *= corr;
#pragma unroll
            for (int d = 0; d < D_; d++) acc[d] *= corr;
#pragma unroll
            for (int j = 0; j < 32; j++) {
                float p = __expf(s[j] - nm);
                row_l += p;
#pragma unroll
                for (int d = 0; d < D_; d++)
                    acc[d] = fmaf(p, v_s[(jb + j) * 65 + d], acc[d]);
            }
            row_max = nm;
        }
    }

    float inv = 1.0f / row_l;
    float* op = g_ao + ((size_t)(b * N_) + n0 + r) * DIM_ + h * D_;
#pragma unroll
    for (int c = 0; c < D_; c += 4) {
        float4 o;
        o.x = acc[c + 0] * inv;
        o.y = acc[c + 1] * inv;
        o.z = acc[c + 2] * inv;
        o.w = acc[c + 3] * inv;
        *(float4*)(op + c) = o;
    }
}

// ---------------------------------------------------------------------------
// Launch
// ---------------------------------------------------------------------------
extern "C" void kernel_launch(void* const* d_in, const int* in_sizes, int n_in,
                              void* d_out, int out_size) {
    const float* x   = (const float*)d_in[0];
    const float* ctx = (const float*)d_in[1];
    const int*   msk = (const int*)d_in[2];
    const float* Wq  = (const float*)d_in[3];
    const float* bq  = (const float*)d_in[4];
    const float* Wkv = (const float*)d_in[5];
    const float* bkv = (const float*)d_in[6];
    const float* Wp  = (const float*)d_in[7];
    const float* bp  = (const float*)d_in[8];
    float* out = (float*)d_out;

    cudaFuncSetAttribute(attn_kernel,
                         cudaFuncAttributeMaxDynamicSharedMemorySize, SMEM_ATTN);

    pack_mask_kernel<<<(B_ * N_) / 8, 256>>>(msk);
    gemm128_kernel<1><<<dim3(DIM_ / 128, B_ * N_ / 128), 256>>>(
        x, Wq, bq, nullptr, B_ * N_, DIM_, DIM_);
    gemm128_kernel<2><<<dim3(2 * DIM_ / 128, B_ * M_ / 128), 256>>>(
        ctx, Wkv, bkv, nullptr, B_ * M_, 2 * DIM_, DIM_);
    attn_kernel<<<dim3(N_ / QROWS, H_, B_), 128, SMEM_ATTN>>>();
    gemm128_kernel<0><<<dim3(DIM_ / 128, B_ * N_ / 128), 256>>>(
        nullptr, Wp, bp, out, B_ * N_, DIM_, DIM_);
}

// round 5
// speedup vs baseline: 1.2809x; 1.2809x over previous
#include <cuda_runtime.h>

// Problem constants
constexpr int B_ = 4, H_ = 16, N_ = 1024, M_ = 1024, D_ = 64, DIM_ = 1024;
constexpr float SCALE_ = 0.125f;   // 64^-0.5

typedef unsigned long long ull;

// Scratch (device globals — no allocation allowed)
__device__ float g_q[(size_t)B_ * H_ * N_ * D_];        // [b,h,n,d]
__device__ float g_k[(size_t)B_ * H_ * M_ * D_];        // [b,h,m,d]
__device__ float g_v[(size_t)B_ * H_ * M_ * D_];        // [b,h,m,d]
__device__ float g_ao[(size_t)B_ * N_ * DIM_];          // [b,n,h*d]
__device__ unsigned g_mbits[(size_t)B_ * N_ * (M_ / 32)]; // packed mask bits

// ---------------------------------------------------------------------------
// Packed fp32x2 helpers (sm_100+ PTX)
// ---------------------------------------------------------------------------
__device__ __forceinline__ ull pack2(float x, float y) {
    ull r; asm("mov.b64 %0, {%1, %2};" : "=l"(r) : "f"(x), "f"(y)); return r;
}
__device__ __forceinline__ float2 unpack2(ull v) {
    float2 f; asm("mov.b64 {%0, %1}, %2;" : "=f"(f.x), "=f"(f.y) : "l"(v)); return f;
}
__device__ __forceinline__ void ffma2(ull& d, ull a, ull b) {
    asm("fma.rn.f32x2 %0, %1, %2, %0;" : "+l"(d) : "l"(a), "l"(b));
}
__device__ __forceinline__ void fmul2(ull& d, ull m) {
    asm("mul.rn.f32x2 %0, %0, %1;" : "+l"(d) : "l"(m));
}

// ---------------------------------------------------------------------------
// Pack int32 mask [b,n,1024] into bitmask words [b,n,32]
// ---------------------------------------------------------------------------
__global__ __launch_bounds__(256) void pack_mask_kernel(const int* __restrict__ mask) {
    int lane = threadIdx.x & 31;
    int row = blockIdx.x * 8 + (threadIdx.x >> 5);   // 0..4095 (b*1024+n)
    const int* mrow = mask + (size_t)row * M_;
    unsigned* brow = g_mbits + (size_t)row * (M_ / 32);
#pragma unroll 4
    for (int w = 0; w < M_ / 32; w++) {
        int v = mrow[w * 32 + lane];
        unsigned bits = __ballot_sync(0xffffffffu, v != 0);
        if (lane == 0) brow[w] = bits;
    }
}

// ---------------------------------------------------------------------------
// Tiled SGEMM with packed f32x2 inner product.
// C[M,N] = A[M,K] @ W[K,N] + bias, with scatter epilogues.
// MODE 0: plain row-major store to C (A is read from g_ao)
// MODE 1: Q projection  -> scatter to g_q [b,h,n,d]
// MODE 2: KV projection -> scatter to g_k / g_v [b,h,m,d]
// ---------------------------------------------------------------------------
template <int MODE>
__global__ __launch_bounds__(256) void gemm128_kernel(
    const float* __restrict__ A, const float* __restrict__ W,
    const float* __restrict__ bias, float* __restrict__ C,
    int M, int N, int K)
{
    __shared__ float As[8][128];   // transposed A tile
    __shared__ float Bs[8][128];

    const float* Aeff = (MODE == 0) ? g_ao : A;

    int tid = threadIdx.x;
    int tx = tid & 15, ty = tid >> 4;
    const float* Ab = Aeff + (size_t)blockIdx.y * 128 * K;
    const float* Wb = W + (size_t)blockIdx.x * 128;
    int aRow = tid >> 1, aC = (tid & 1) * 4;
    int bRow = tid >> 5, bC = (tid & 31) * 4;

    ull acc2[8][4];
#pragma unroll
    for (int i = 0; i < 8; i++)
#pragma unroll
        for (int j = 0; j < 4; j++) acc2[i][j] = 0ull;

    for (int k0 = 0; k0 < K; k0 += 8) {
        float4 a4 = *(const float4*)(Ab + (size_t)aRow * K + k0 + aC);
        As[aC + 0][aRow] = a4.x;
        As[aC + 1][aRow] = a4.y;
        As[aC + 2][aRow] = a4.z;
        As[aC + 3][aRow] = a4.w;
        float4 b4 = *(const float4*)(Wb + (size_t)(k0 + bRow) * N + bC);
        *(float4*)&Bs[bRow][bC] = b4;
        __syncthreads();
#pragma unroll
        for (int kk = 0; kk < 8; kk++) {
            float4 aa0 = *(const float4*)&As[kk][ty * 8];
            float4 aa1 = *(const float4*)&As[kk][ty * 8 + 4];
            float4 bb0 = *(const float4*)&Bs[kk][tx * 8];
            float4 bb1 = *(const float4*)&Bs[kk][tx * 8 + 4];
            ull b2[4];
            b2[0] = pack2(bb0.x, bb0.y);
            b2[1] = pack2(bb0.z, bb0.w);
            b2[2] = pack2(bb1.x, bb1.y);
            b2[3] = pack2(bb1.z, bb1.w);
            float av[8] = {aa0.x, aa0.y, aa0.z, aa0.w, aa1.x, aa1.y, aa1.z, aa1.w};
#pragma unroll
            for (int i = 0; i < 8; i++) {
                ull ad = pack2(av[i], av[i]);
                ffma2(acc2[i][0], ad, b2[0]);
                ffma2(acc2[i][1], ad, b2[1]);
                ffma2(acc2[i][2], ad, b2[2]);
                ffma2(acc2[i][3], ad, b2[3]);
            }
        }
        __syncthreads();
    }

#pragma unroll
    for (int i = 0; i < 8; i++) {
        int gRow = blockIdx.y * 128 + ty * 8 + i;
#pragma unroll
        for (int j2 = 0; j2 < 4; j2++) {
            float2 v2 = unpack2(acc2[i][j2]);
            float vv[2] = {v2.x, v2.y};
#pragma unroll
            for (int u = 0; u < 2; u++) {
                int j = j2 * 2 + u;
                int gCol = blockIdx.x * 128 + tx * 8 + j;
                float val = vv[u] + bias[gCol];
                if (MODE == 0) {
                    C[(size_t)gRow * N + gCol] = val;
                } else if (MODE == 1) {
                    int bb = gRow >> 10, n = gRow & 1023;
                    int h = gCol >> 6, d = gCol & 63;
                    g_q[(((size_t)(bb * H_ + h)) * N_ + n) * D_ + d] = val;
                } else {
                    int bb = gRow >> 10, m = gRow & 1023;
                    int cc = gCol & 1023;
                    int h = cc >> 6, d = cc & 63;
                    float* dst = (gCol < DIM_) ? g_k : g_v;
                    dst[(((size_t)(bb * H_ + h)) * M_ + m) * D_ + d] = val;
                }
            }
        }
    }
}

// ---------------------------------------------------------------------------
// Fused flash attention as two register-blocked GEMMs per tile.
// grid (N/128, H, B), 256 threads. Thread (ty,tx): rows ty*8..+7, cols tx*4..+3.
// ---------------------------------------------------------------------------
constexpr int QR = 128;    // q rows per CTA
constexpr int KT = 64;     // k/v rows per tile
constexpr int PT_STRIDE = 132;
constexpr int SMEM_ATTN = (64 * 128 + 64 * 64 + 64 * 64 + 64 * PT_STRIDE) * 4; // 99328 B

__global__ __launch_bounds__(256) void attn_kernel() {
    extern __shared__ float sm[];
    float* Qt = sm;                    // [64 kk][128 rows]  (transposed, pre-scaled)
    float* Kt = Qt + 64 * 128;         // [64 kk][64 krows]  (transposed)
    float* Vs = Kt + 64 * 64;          // [64 krows][64 d]   (row-major)
    float* Pt = Vs + 64 * 64;          // [64 cols][132]     (transposed P)

    int tid = threadIdx.x;
    int tx = tid & 15, ty = tid >> 4;
    int r0 = ty * 8, c0 = tx * 4;
    int n0 = blockIdx.x * QR;
    int h = blockIdx.y, b = blockIdx.z;

    const float* qp = g_q + (((size_t)(b * H_ + h)) * N_ + n0) * D_;
    const float* kp = g_k + ((size_t)(b * H_ + h)) * M_ * D_;
    const float* vp = g_v + ((size_t)(b * H_ + h)) * M_ * D_;
    const unsigned* mbp = g_mbits + ((size_t)(b * N_) + n0) * (M_ / 32);

    // Load Q tile transposed + scaled: thread -> row tid>>1, d-half (tid&1)*32
    {
        int row = tid >> 1, dh = (tid & 1) * 32;
#pragma unroll
        for (int c = 0; c < 32; c += 4) {
            float4 f = *(const float4*)(qp + (size_t)row * D_ + dh + c);
            Qt[(dh + c + 0) * 128 + row] = f.x * SCALE_;
            Qt[(dh + c + 1) * 128 + row] = f.y * SCALE_;
            Qt[(dh + c + 2) * 128 + row] = f.z * SCALE_;
            Qt[(dh + c + 3) * 128 + row] = f.w * SCALE_;
        }
    }

    ull acc2[8][2];
    float row_max[8], row_l[8];
#pragma unroll
    for (int i = 0; i < 8; i++) {
        acc2[i][0] = 0ull; acc2[i][1] = 0ull;
        row_max[i] = -1e30f; row_l[i] = 0.f;
    }

#pragma unroll 1
    for (int m0 = 0; m0 < M_; m0 += KT) {
        __syncthreads();   // prev tile fully consumed (and Qt ready on iter 0)
        // Load K (transposed) and V (row-major): thread -> krow tid&63, d-quarter
        {
            int rr = tid & 63, dq = (tid >> 6) * 16;
#pragma unroll
            for (int c = 0; c < 16; c += 4) {
                float4 f = *(const float4*)(kp + (size_t)(m0 + rr) * D_ + dq + c);
                Kt[(dq + c + 0) * 64 + rr] = f.x;
                Kt[(dq + c + 1) * 64 + rr] = f.y;
                Kt[(dq + c + 2) * 64 + rr] = f.z;
                Kt[(dq + c + 3) * 64 + rr] = f.w;
                float4 g = *(const float4*)(vp + (size_t)(m0 + rr) * D_ + dq + c);
                *(float4*)&Vs[rr * 64 + dq + c] = g;
            }
        }
        __syncthreads();

        // ---- Phase 1: S = Q @ K^T (8x4 microtile via f32x2) ----
        ull s2[8][2];
#pragma unroll
        for (int i = 0; i < 8; i++) { s2[i][0] = 0ull; s2[i][1] = 0ull; }
#pragma unroll 2
        for (int kk = 0; kk < 64; kk++) {
            float4 qa = *(const float4*)&Qt[kk * 128 + r0];
            float4 qb = *(const float4*)&Qt[kk * 128 + r0 + 4];
            float4 kv = *(const float4*)&Kt[kk * 64 + c0];
            ull k2a = pack2(kv.x, kv.y);
            ull k2b = pack2(kv.z, kv.w);
            float qs[8] = {qa.x, qa.y, qa.z, qa.w, qb.x, qb.y, qb.z, qb.w};
#pragma unroll
            for (int rr = 0; rr < 8; rr++) {
                ull qq = pack2(qs[rr], qs[rr]);
                ffma2(s2[rr][0], qq, k2a);
                ffma2(s2[rr][1], qq, k2b);
            }
        }

        // ---- Mask + online softmax ----
        float ps[8][4];
        int w = (m0 >> 5) + (c0 >> 5);
        int bit0 = c0 & 31;
#pragma unroll
        for (int rr = 0; rr < 8; rr++) {
            unsigned mb = mbp[(size_t)(r0 + rr) * (M_ / 32) + w];
            float2 sA = unpack2(s2[rr][0]);
            float2 sB = unpack2(s2[rr][1]);
            float sv[4] = {sA.x, sA.y, sB.x, sB.y};
#pragma unroll
            for (int cc = 0; cc < 4; cc++)
                if (!((mb >> (bit0 + cc)) & 1u)) sv[cc] = -INFINITY;
            float tmax = fmaxf(fmaxf(sv[0], sv[1]), fmaxf(sv[2], sv[3]));
#pragma unroll
            for (int d = 1; d < 16; d <<= 1)
                tmax = fmaxf(tmax, __shfl_xor_sync(0xffffffffu, tmax, d));
            float nm = fmaxf(fmaxf(row_max[rr], tmax), -1e30f);
            float corr = __expf(row_max[rr] - nm);
            row_max[rr] = nm;
            float lsum = 0.f;
#pragma unroll
            for (int cc = 0; cc < 4; cc++) {
                float p = __expf(sv[cc] - nm);
                ps[rr][cc] = p;
                lsum += p;
            }
#pragma unroll
            for (int d = 1; d < 16; d <<= 1)
                lsum += __shfl_xor_sync(0xffffffffu, lsum, d);
            row_l[rr] = row_l[rr] * corr + lsum;
            ull c2 = pack2(corr, corr);
            fmul2(acc2[rr][0], c2);
            fmul2(acc2[rr][1], c2);
        }

        // write P transposed: Pt[col][row]
#pragma unroll
        for (int jj = 0; jj < 4; jj++) {
            float4 f0 = make_float4(ps[0][jj], ps[1][jj], ps[2][jj], ps[3][jj]);
            float4 f1 = make_float4(ps[4][jj], ps[5][jj], ps[6][jj], ps[7][jj]);
            *(float4*)&Pt[(c0 + jj) * PT_STRIDE + r0] = f0;
            *(float4*)&Pt[(c0 + jj) * PT_STRIDE + r0 + 4] = f1;
        }
        __syncthreads();

        // ---- Phase 2: O += P @ V (8x4 microtile via f32x2) ----
#pragma unroll 2
        for (int j = 0; j < KT; j++) {
            float4 pa = *(const float4*)&Pt[j * PT_STRIDE + r0];
            float4 pb = *(const float4*)&Pt[j * PT_STRIDE + r0 + 4];
            float4 vv = *(const float4*)&Vs[j * 64 + c0];
            ull v2a = pack2(vv.x, vv.y);
            ull v2b = pack2(vv.z, vv.w);
            float pf[8] = {pa.x, pa.y, pa.z, pa.w, pb.x, pb.y, pb.z, pb.w};
#pragma unroll
            for (int rr = 0; rr < 8; rr++) {
                ull pp = pack2(pf[rr], pf[rr]);
                ffma2(acc2[rr][0], pp, v2a);
                ffma2(acc2[rr][1], pp, v2b);
            }
        }
    }

    // Epilogue: normalize and store to g_ao [b,n,h*d]
#pragma unroll
    for (int rr = 0; rr < 8; rr++) {
        float inv = 1.0f / row_l[rr];
        float2 o0 = unpack2(acc2[rr][0]);
        float2 o1 = unpack2(acc2[rr][1]);
        float4 o = make_float4(o0.x * inv, o0.y * inv, o1.x * inv, o1.y * inv);
        *(float4*)(g_ao + ((size_t)(b * N_) + n0 + r0 + rr) * DIM_ + h * D_ + c0) = o;
    }
}

// ---------------------------------------------------------------------------
// Launch
// ---------------------------------------------------------------------------
extern "C" void kernel_launch(void* const* d_in, const int* in_sizes, int n_in,
                              void* d_out, int out_size) {
    const float* x   = (const float*)d_in[0];
    const float* ctx = (const float*)d_in[1];
    const int*   msk = (const int*)d_in[2];
    const float* Wq  = (const float*)d_in[3];
    const float* bq  = (const float*)d_in[4];
    const float* Wkv = (const float*)d_in[5];
    const float* bkv = (const float*)d_in[6];
    const float* Wp  = (const float*)d_in[7];
    const float* bp  = (const float*)d_in[8];
    float* out = (float*)d_out;

    cudaFuncSetAttribute(attn_kernel,
                         cudaFuncAttributeMaxDynamicSharedMemorySize, SMEM_ATTN);

    pack_mask_kernel<<<(B_ * N_) / 8, 256>>>(msk);
    gemm128_kernel<1><<<dim3(DIM_ / 128, B_ * N_ / 128), 256>>>(
        x, Wq, bq, nullptr, B_ * N_, DIM_, DIM_);
    gemm128_kernel<2><<<dim3(2 * DIM_ / 128, B_ * M_ / 128), 256>>>(
        ctx, Wkv, bkv, nullptr, B_ * M_, 2 * DIM_, DIM_);
    attn_kernel<<<dim3(N_ / QR, H_, B_), 256, SMEM_ATTN>>>();
    gemm128_kernel<0><<<dim3(DIM_ / 128, B_ * N_ / 128), 256>>>(
        nullptr, Wp, bp, out, B_ * N_, DIM_, DIM_);
}

// round 9
// speedup vs baseline: 1.7340x; 1.3537x over previous
#include <cuda_runtime.h>
#include <cstdint>

// Problem constants
constexpr int B_ = 4, H_ = 16, N_ = 1024, M_ = 1024, D_ = 64, DIM_ = 1024;
constexpr float SCALE_ = 0.125f;   // 64^-0.5

typedef unsigned long long ull;

// Scratch (device globals — no allocation allowed)
__device__ float g_q[(size_t)B_ * H_ * N_ * D_];        // [b,h,n,d]
__device__ float g_k[(size_t)B_ * H_ * M_ * D_];        // [b,h,m,d]
__device__ float g_v[(size_t)B_ * H_ * M_ * D_];        // [b,h,m,d]
__device__ float g_ao[(size_t)B_ * N_ * DIM_];          // [b,n,h*d]
__device__ unsigned g_mbits[(size_t)B_ * N_ * (M_ / 32)]; // packed mask bits

// ---------------------------------------------------------------------------
// Helpers
// ---------------------------------------------------------------------------
__device__ __forceinline__ float to_tf32(float x) {
    float r; asm("cvt.rna.tf32.f32 %0, %1;" : "=f"(r) : "f"(x)); return r;
}
__device__ __forceinline__ ull pack2(float x, float y) {
    ull r; asm("mov.b64 %0, {%1, %2};" : "=l"(r) : "f"(x), "f"(y)); return r;
}
__device__ __forceinline__ float2 unpack2(ull v) {
    float2 f; asm("mov.b64 {%0, %1}, %2;" : "=f"(f.x), "=f"(f.y) : "l"(v)); return f;
}
__device__ __forceinline__ void ffma2(ull& d, ull a, ull b) {
    asm("fma.rn.f32x2 %0, %1, %2, %0;" : "+l"(d) : "l"(a), "l"(b));
}
__device__ __forceinline__ void fmul2(ull& d, ull m) {
    asm("mul.rn.f32x2 %0, %0, %1;" : "+l"(d) : "l"(m));
}
// mma.sync m16n8k8 tf32 (works on non-'a' targets; HMMA fallback on Blackwell)
__device__ __forceinline__ void mma_1688(float* d, const uint32_t* a, const uint32_t* b) {
    asm volatile(
        "mma.sync.aligned.m16n8k8.row.col.f32.tf32.tf32.f32 "
        "{%0,%1,%2,%3}, {%4,%5,%6,%7}, {%8,%9}, {%0,%1,%2,%3};"
        : "+f"(d[0]), "+f"(d[1]), "+f"(d[2]), "+f"(d[3])
        : "r"(a[0]), "r"(a[1]), "r"(a[2]), "r"(a[3]), "r"(b[0]), "r"(b[1]));
}

// ---------------------------------------------------------------------------
// Pack int32 mask [b,n,1024] into bitmask words [b,n,32]
// ---------------------------------------------------------------------------
__global__ __launch_bounds__(256) void pack_mask_kernel(const int* __restrict__ mask) {
    int lane = threadIdx.x & 31;
    int row = blockIdx.x * 8 + (threadIdx.x >> 5);
    const int* mrow = mask + (size_t)row * M_;
    unsigned* brow = g_mbits + (size_t)row * (M_ / 32);
#pragma unroll 4
    for (int w = 0; w < M_ / 32; w++) {
        int v = mrow[w * 32 + lane];
        unsigned bits = __ballot_sync(0xffffffffu, v != 0);
        if (lane == 0) brow[w] = bits;
    }
}

// ---------------------------------------------------------------------------
// HMMA tf32 GEMM: C[128x128 tile] = A[M,K] @ W[K,N] + bias
// 256 thr = 8 warps (2x4), warp tile 64x32, K-stage 32, double-buffered.
// MODE 0: C row-major (A = g_ao)   MODE 1: Q scatter   MODE 2: KV scatter
// ---------------------------------------------------------------------------
constexpr int AS_STRIDE = 36;                 // words per A smem row (32+4 pad)
constexpr int BS_STRIDE = 136;                // words per B smem row (128+8 pad)
constexpr int AS_BYTES = 128 * AS_STRIDE * 4; // 18432
constexpr int BS_BYTES = 32 * BS_STRIDE * 4;  // 17408
constexpr int SMEM_GEMM = 2 * (AS_BYTES + BS_BYTES); // 71680

template <int MODE>
__global__ __launch_bounds__(256) void mma_gemm(
    const float* __restrict__ A, const float* __restrict__ W,
    const float* __restrict__ bias, float* __restrict__ C,
    int Mrows, int Ncols, int K)
{
    extern __shared__ char smem[];
    float* As[2] = { (float*)smem, (float*)(smem + AS_BYTES) };
    float* Bs[2] = { (float*)(smem + 2 * AS_BYTES),
                     (float*)(smem + 2 * AS_BYTES + BS_BYTES) };

    const float* Aeff = (MODE == 0) ? g_ao : A;
    int tid = threadIdx.x;
    int wid = tid >> 5, lane = tid & 31;
    int g = lane >> 2, lk = lane & 3;
    int wm = (wid & 1) * 64, wn = (wid >> 1) * 32;
    int bM = blockIdx.y * 128, bN = blockIdx.x * 128;

    const float* Ab = Aeff + (size_t)bM * K;
    const float* Wb = W + bN;

    float acc[4][4][4];
#pragma unroll
    for (int mt = 0; mt < 4; mt++)
#pragma unroll
        for (int nt = 0; nt < 4; nt++)
#pragma unroll
            for (int i = 0; i < 4; i++) acc[mt][nt][i] = 0.f;

    float4 aR[4], bR[4];
    // prologue: fetch chunk 0
#pragma unroll
    for (int it = 0; it < 4; it++) {
        int i = tid + it * 256;
        aR[it] = *(const float4*)(Ab + (size_t)(i >> 3) * K + (i & 7) * 4);
        bR[it] = *(const float4*)(Wb + (size_t)(i >> 5) * Ncols + (i & 31) * 4);
    }
    const int NCH = K / 32;
#pragma unroll 1
    for (int ch = 0; ch < NCH; ch++) {
        int st = ch & 1;
        // store prefetched regs (tf32-rounded) into stage st
#pragma unroll
        for (int it = 0; it < 4; it++) {
            int i = tid + it * 256;
            float* pa = &As[st][(i >> 3) * AS_STRIDE + (i & 7) * 4];
            pa[0] = to_tf32(aR[it].x); pa[1] = to_tf32(aR[it].y);
            pa[2] = to_tf32(aR[it].z); pa[3] = to_tf32(aR[it].w);
            float* pb = &Bs[st][(i >> 5) * BS_STRIDE + (i & 31) * 4];
            pb[0] = to_tf32(bR[it].x); pb[1] = to_tf32(bR[it].y);
            pb[2] = to_tf32(bR[it].z); pb[3] = to_tf32(bR[it].w);
        }
        __syncthreads();
        // prefetch next chunk
        if (ch + 1 < NCH) {
            int k0 = (ch + 1) * 32;
#pragma unroll
            for (int it = 0; it < 4; it++) {
                int i = tid + it * 256;
                aR[it] = *(const float4*)(Ab + (size_t)(i >> 3) * K + k0 + (i & 7) * 4);
                bR[it] = *(const float4*)(Wb + (size_t)(k0 + (i >> 5)) * Ncols + (i & 31) * 4);
            }
        }
        // compute on stage st
        const uint32_t* As32 = (const uint32_t*)As[st];
        const uint32_t* Bs32 = (const uint32_t*)Bs[st];
#pragma unroll
        for (int ks = 0; ks < 4; ks++) {
            int kk = ks * 8;
            uint32_t a[4][4], b[4][2];
#pragma unroll
            for (int mt = 0; mt < 4; mt++) {
                int r = wm + mt * 16 + g;
                a[mt][0] = As32[r * AS_STRIDE + kk + lk];
                a[mt][1] = As32[(r + 8) * AS_STRIDE + kk + lk];
                a[mt][2] = As32[r * AS_STRIDE + kk + lk + 4];
                a[mt][3] = As32[(r + 8) * AS_STRIDE + kk + lk + 4];
            }
#pragma unroll
            for (int nt = 0; nt < 4; nt++) {
                int c = wn + nt * 8 + g;
                b[nt][0] = Bs32[(kk + lk) * BS_STRIDE + c];
                b[nt][1] = Bs32[(kk + lk + 4) * BS_STRIDE + c];
            }
#pragma unroll
            for (int mt = 0; mt < 4; mt++)
#pragma unroll
                for (int nt = 0; nt < 4; nt++)
                    mma_1688(acc[mt][nt], a[mt], b[nt]);
        }
        __syncthreads();
    }

    // Epilogue: c0,c1 -> row g, cols 2lk,2lk+1 ; c2,c3 -> row g+8
#pragma unroll
    for (int mt = 0; mt < 4; mt++) {
#pragma unroll
        for (int nt = 0; nt < 4; nt++) {
            int gCol = bN + wn + nt * 8 + 2 * lk;
            float bx = bias[gCol], by = bias[gCol + 1];
#pragma unroll
            for (int half = 0; half < 2; half++) {
                int gRow = bM + wm + mt * 16 + g + half * 8;
                float vx = acc[mt][nt][half * 2 + 0] + bx;
                float vy = acc[mt][nt][half * 2 + 1] + by;
                if (MODE == 0) {
                    *(float2*)(C + (size_t)gRow * Ncols + gCol) = make_float2(vx, vy);
                } else if (MODE == 1) {
                    int bb = gRow >> 10, n = gRow & 1023;
                    int h = gCol >> 6, d = gCol & 63;
                    *(float2*)(g_q + (((size_t)(bb * H_ + h)) * N_ + n) * D_ + d) =
                        make_float2(vx, vy);
                } else {
                    int bb = gRow >> 10, m = gRow & 1023;
                    int cc = gCol & 1023;
                    int h = cc >> 6, d = cc & 63;
                    float* dst = (gCol < DIM_) ? g_k : g_v;
                    *(float2*)(dst + (((size_t)(bb * H_ + h)) * M_ + m) * D_ + d) =
                        make_float2(vx, vy);
                }
            }
        }
    }
}

// ---------------------------------------------------------------------------
// Fused flash attention (scalar f32x2) — unchanged (535us, fma-bound)
// ---------------------------------------------------------------------------
constexpr int QR = 128;
constexpr int KT = 64;
constexpr int PT_STRIDE = 132;
constexpr int SMEM_ATTN = (64 * 128 + 64 * 64 + 64 * 64 + 64 * PT_STRIDE) * 4;

__global__ __launch_bounds__(256) void attn_kernel() {
    extern __shared__ float sm[];
    float* Qt = sm;
    float* Kt = Qt + 64 * 128;
    float* Vs = Kt + 64 * 64;
    float* Pt = Vs + 64 * 64;

    int tid = threadIdx.x;
    int tx = tid & 15, ty = tid >> 4;
    int r0 = ty * 8, c0 = tx * 4;
    int n0 = blockIdx.x * QR;
    int h = blockIdx.y, b = blockIdx.z;

    const float* qp = g_q + (((size_t)(b * H_ + h)) * N_ + n0) * D_;
    const float* kp = g_k + ((size_t)(b * H_ + h)) * M_ * D_;
    const float* vp = g_v + ((size_t)(b * H_ + h)) * M_ * D_;
    const unsigned* mbp = g_mbits + ((size_t)(b * N_) + n0) * (M_ / 32);

    {
        int row = tid >> 1, dh = (tid & 1) * 32;
#pragma unroll
        for (int c = 0; c < 32; c += 4) {
            float4 f = *(const float4*)(qp + (size_t)row * D_ + dh + c);
            Qt[(dh + c + 0) * 128 + row] = f.x * SCALE_;
            Qt[(dh + c + 1) * 128 + row] = f.y * SCALE_;
            Qt[(dh + c + 2) * 128 + row] = f.z * SCALE_;
            Qt[(dh + c + 3) * 128 + row] = f.w * SCALE_;
        }
    }

    ull acc2[8][2];
    float row_max[8], row_l[8];
#pragma unroll
    for (int i = 0; i < 8; i++) {
        acc2[i][0] = 0ull; acc2[i][1] = 0ull;
        row_max[i] = -1e30f; row_l[i] = 0.f;
    }

#pragma unroll 1
    for (int m0 = 0; m0 < M_; m0 += KT) {
        __syncthreads();
        {
            int rr = tid & 63, dq = (tid >> 6) * 16;
#pragma unroll
            for (int c = 0; c < 16; c += 4) {
                float4 f = *(const float4*)(kp + (size_t)(m0 + rr) * D_ + dq + c);
                Kt[(dq + c + 0) * 64 + rr] = f.x;
                Kt[(dq + c + 1) * 64 + rr] = f.y;
                Kt[(dq + c + 2) * 64 + rr] = f.z;
                Kt[(dq + c + 3) * 64 + rr] = f.w;
                float4 g = *(const float4*)(vp + (size_t)(m0 + rr) * D_ + dq + c);
                *(float4*)&Vs[rr * 64 + dq + c] = g;
            }
        }
        __syncthreads();

        ull s2[8][2];
#pragma unroll
        for (int i = 0; i < 8; i++) { s2[i][0] = 0ull; s2[i][1] = 0ull; }
#pragma unroll 2
        for (int kk = 0; kk < 64; kk++) {
            float4 qa = *(const float4*)&Qt[kk * 128 + r0];
            float4 qb = *(const float4*)&Qt[kk * 128 + r0 + 4];
            float4 kv = *(const float4*)&Kt[kk * 64 + c0];
            ull k2a = pack2(kv.x, kv.y);
            ull k2b = pack2(kv.z, kv.w);
            float qs[8] = {qa.x, qa.y, qa.z, qa.w, qb.x, qb.y, qb.z, qb.w};
#pragma unroll
            for (int rr = 0; rr < 8; rr++) {
                ull qq = pack2(qs[rr], qs[rr]);
                ffma2(s2[rr][0], qq, k2a);
                ffma2(s2[rr][1], qq, k2b);
            }
        }

        float ps[8][4];
        int w = (m0 >> 5) + (c0 >> 5);
        int bit0 = c0 & 31;
#pragma unroll
        for (int rr = 0; rr < 8; rr++) {
            unsigned mb = mbp[(size_t)(r0 + rr) * (M_ / 32) + w];
            float2 sA = unpack2(s2[rr][0]);
            float2 sB = unpack2(s2[rr][1]);
            float sv[4] = {sA.x, sA.y, sB.x, sB.y};
#pragma unroll
            for (int cc = 0; cc < 4; cc++)
                if (!((mb >> (bit0 + cc)) & 1u)) sv[cc] = -INFINITY;
            float tmax = fmaxf(fmaxf(sv[0], sv[1]), fmaxf(sv[2], sv[3]));
#pragma unroll
            for (int d = 1; d < 16; d <<= 1)
                tmax = fmaxf(tmax, __shfl_xor_sync(0xffffffffu, tmax, d));
            float nm = fmaxf(fmaxf(row_max[rr], tmax), -1e30f);
            float corr = __expf(row_max[rr] - nm);
            row_max[rr] = nm;
            float lsum = 0.f;
#pragma unroll
            for (int cc = 0; cc < 4; cc++) {
                float p = __expf(sv[cc] - nm);
                ps[rr][cc] = p;
                lsum += p;
            }
#pragma unroll
            for (int d = 1; d < 16; d <<= 1)
                lsum += __shfl_xor_sync(0xffffffffu, lsum, d);
            row_l[rr] = row_l[rr] * corr + lsum;
            ull c2 = pack2(corr, corr);
            fmul2(acc2[rr][0], c2);
            fmul2(acc2[rr][1], c2);
        }

#pragma unroll
        for (int jj = 0; jj < 4; jj++) {
            float4 f0 = make_float4(ps[0][jj], ps[1][jj], ps[2][jj], ps[3][jj]);
            float4 f1 = make_float4(ps[4][jj], ps[5][jj], ps[6][jj], ps[7][jj]);
            *(float4*)&Pt[(c0 + jj) * PT_STRIDE + r0] = f0;
            *(float4*)&Pt[(c0 + jj) * PT_STRIDE + r0 + 4] = f1;
        }
        __syncthreads();

#pragma unroll 2
        for (int j = 0; j < KT; j++) {
            float4 pa = *(const float4*)&Pt[j * PT_STRIDE + r0];
            float4 pb = *(const float4*)&Pt[j * PT_STRIDE + r0 + 4];
            float4 vv = *(const float4*)&Vs[j * 64 + c0];
            ull v2a = pack2(vv.x, vv.y);
            ull v2b = pack2(vv.z, vv.w);
            float pf[8] = {pa.x, pa.y, pa.z, pa.w, pb.x, pb.y, pb.z, pb.w};
#pragma unroll
            for (int rr = 0; rr < 8; rr++) {
                ull pp = pack2(pf[rr], pf[rr]);
                ffma2(acc2[rr][0], pp, v2a);
                ffma2(acc2[rr][1], pp, v2b);
            }
        }
    }

#pragma unroll
    for (int rr = 0; rr < 8; rr++) {
        float inv = 1.0f / row_l[rr];
        float2 o0 = unpack2(acc2[rr][0]);
        float2 o1 = unpack2(acc2[rr][1]);
        float4 o = make_float4(o0.x * inv, o0.y * inv, o1.x * inv, o1.y * inv);
        *(float4*)(g_ao + ((size_t)(b * N_) + n0 + r0 + rr) * DIM_ + h * D_ + c0) = o;
    }
}

// ---------------------------------------------------------------------------
// Launch
// ---------------------------------------------------------------------------
extern "C" void kernel_launch(void* const* d_in, const int* in_sizes, int n_in,
                              void* d_out, int out_size) {
    const float* x   = (const float*)d_in[0];
    const float* ctx = (const float*)d_in[1];
    const int*   msk = (const int*)d_in[2];
    const float* Wq  = (const float*)d_in[3];
    const float* bq  = (const float*)d_in[4];
    const float* Wkv = (const float*)d_in[5];
    const float* bkv = (const float*)d_in[6];
    const float* Wp  = (const float*)d_in[7];
    const float* bp  = (const float*)d_in[8];
    float* out = (float*)d_out;

    cudaFuncSetAttribute(attn_kernel,
                         cudaFuncAttributeMaxDynamicSharedMemorySize, SMEM_ATTN);
    cudaFuncSetAttribute(mma_gemm<0>,
                         cudaFuncAttributeMaxDynamicSharedMemorySize, SMEM_GEMM);
    cudaFuncSetAttribute(mma_gemm<1>,
                         cudaFuncAttributeMaxDynamicSharedMemorySize, SMEM_GEMM);
    cudaFuncSetAttribute(mma_gemm<2>,
                         cudaFuncAttributeMaxDynamicSharedMemorySize, SMEM_GEMM);

    pack_mask_kernel<<<(B_ * N_) / 8, 256>>>(msk);
    mma_gemm<1><<<dim3(DIM_ / 128, B_ * N_ / 128), 256, SMEM_GEMM>>>(
        x, Wq, bq, nullptr, B_ * N_, DIM_, DIM_);
    mma_gemm<2><<<dim3(2 * DIM_ / 128, B_ * M_ / 128), 256, SMEM_GEMM>>>(
        ctx, Wkv, bkv, nullptr, B_ * M_, 2 * DIM_, DIM_);
    attn_kernel<<<dim3(N_ / QR, H_, B_), 256, SMEM_ATTN>>>();
    mma_gemm<0><<<dim3(DIM_ / 128, B_ * N_ / 128), 256, SMEM_GEMM>>>(
        nullptr, Wp, bp, out, B_ * N_, DIM_, DIM_);
}

// round 10
// speedup vs baseline: 2.4918x; 1.4370x over previous
#include <cuda_runtime.h>
#include <cstdint>

// Problem constants
constexpr int B_ = 4, H_ = 16, N_ = 1024, M_ = 1024, D_ = 64, DIM_ = 1024;
constexpr float SCALE_ = 0.125f;   // 64^-0.5

typedef unsigned long long ull;

// Scratch (device globals — no allocation allowed)
__device__ float g_q[(size_t)B_ * H_ * N_ * D_];        // [b,h,n,d]
__device__ float g_k[(size_t)B_ * H_ * M_ * D_];        // [b,h,m,d]
__device__ float g_v[(size_t)B_ * H_ * M_ * D_];        // [b,h,m,d]
__device__ float g_ao[(size_t)B_ * N_ * DIM_];          // [b,n,h*d]
__device__ unsigned g_mbits[(size_t)B_ * N_ * (M_ / 32)]; // packed mask bits

// ---------------------------------------------------------------------------
// Helpers
// ---------------------------------------------------------------------------
__device__ __forceinline__ float to_tf32(float x) {
    float r; asm("cvt.rna.tf32.f32 %0, %1;" : "=f"(r) : "f"(x)); return r;
}
// mma.sync m16n8k8 tf32 (legal on non-'a' targets; HMMA path on Blackwell)
__device__ __forceinline__ void mma_1688(float* d, const uint32_t* a, const uint32_t* b) {
    asm volatile(
        "mma.sync.aligned.m16n8k8.row.col.f32.tf32.tf32.f32 "
        "{%0,%1,%2,%3}, {%4,%5,%6,%7}, {%8,%9}, {%0,%1,%2,%3};"
        : "+f"(d[0]), "+f"(d[1]), "+f"(d[2]), "+f"(d[3])
        : "r"(a[0]), "r"(a[1]), "r"(a[2]), "r"(a[3]), "r"(b[0]), "r"(b[1]));
}

// ---------------------------------------------------------------------------
// Pack int32 mask [b,n,1024] into bitmask words [b,n,32]
// ---------------------------------------------------------------------------
__global__ __launch_bounds__(256) void pack_mask_kernel(const int* __restrict__ mask) {
    int lane = threadIdx.x & 31;
    int row = blockIdx.x * 8 + (threadIdx.x >> 5);
    const int* mrow = mask + (size_t)row * M_;
    unsigned* brow = g_mbits + (size_t)row * (M_ / 32);
#pragma unroll 4
    for (int w = 0; w < M_ / 32; w++) {
        int v = mrow[w * 32 + lane];
        unsigned bits = __ballot_sync(0xffffffffu, v != 0);
        if (lane == 0) brow[w] = bits;
    }
}

// ---------------------------------------------------------------------------
// HMMA tf32 GEMM (unchanged from R8): C[128x128] = A[M,K] @ W[K,N] + bias
// ---------------------------------------------------------------------------
constexpr int AS_STRIDE = 36;
constexpr int BS_STRIDE = 136;
constexpr int AS_BYTES = 128 * AS_STRIDE * 4;
constexpr int BS_BYTES = 32 * BS_STRIDE * 4;
constexpr int SMEM_GEMM = 2 * (AS_BYTES + BS_BYTES); // 71680

template <int MODE>
__global__ __launch_bounds__(256) void mma_gemm(
    const float* __restrict__ A, const float* __restrict__ W,
    const float* __restrict__ bias, float* __restrict__ C,
    int Mrows, int Ncols, int K)
{
    extern __shared__ char smem[];
    float* As[2] = { (float*)smem, (float*)(smem + AS_BYTES) };
    float* Bs[2] = { (float*)(smem + 2 * AS_BYTES),
                     (float*)(smem + 2 * AS_BYTES + BS_BYTES) };

    const float* Aeff = (MODE == 0) ? g_ao : A;
    int tid = threadIdx.x;
    int wid = tid >> 5, lane = tid & 31;
    int g = lane >> 2, lk = lane & 3;
    int wm = (wid & 1) * 64, wn = (wid >> 1) * 32;
    int bM = blockIdx.y * 128, bN = blockIdx.x * 128;

    const float* Ab = Aeff + (size_t)bM * K;
    const float* Wb = W + bN;

    float acc[4][4][4];
#pragma unroll
    for (int mt = 0; mt < 4; mt++)
#pragma unroll
        for (int nt = 0; nt < 4; nt++)
#pragma unroll
            for (int i = 0; i < 4; i++) acc[mt][nt][i] = 0.f;

    float4 aR[4], bR[4];
#pragma unroll
    for (int it = 0; it < 4; it++) {
        int i = tid + it * 256;
        aR[it] = *(const float4*)(Ab + (size_t)(i >> 3) * K + (i & 7) * 4);
        bR[it] = *(const float4*)(Wb + (size_t)(i >> 5) * Ncols + (i & 31) * 4);
    }
    const int NCH = K / 32;
#pragma unroll 1
    for (int ch = 0; ch < NCH; ch++) {
        int st = ch & 1;
#pragma unroll
        for (int it = 0; it < 4; it++) {
            int i = tid + it * 256;
            float* pa = &As[st][(i >> 3) * AS_STRIDE + (i & 7) * 4];
            pa[0] = to_tf32(aR[it].x); pa[1] = to_tf32(aR[it].y);
            pa[2] = to_tf32(aR[it].z); pa[3] = to_tf32(aR[it].w);
            float* pb = &Bs[st][(i >> 5) * BS_STRIDE + (i & 31) * 4];
            pb[0] = to_tf32(bR[it].x); pb[1] = to_tf32(bR[it].y);
            pb[2] = to_tf32(bR[it].z); pb[3] = to_tf32(bR[it].w);
        }
        __syncthreads();
        if (ch + 1 < NCH) {
            int k0 = (ch + 1) * 32;
#pragma unroll
            for (int it = 0; it < 4; it++) {
                int i = tid + it * 256;
                aR[it] = *(const float4*)(Ab + (size_t)(i >> 3) * K + k0 + (i & 7) * 4);
                bR[it] = *(const float4*)(Wb + (size_t)(k0 + (i >> 5)) * Ncols + (i & 31) * 4);
            }
        }
        const uint32_t* As32 = (const uint32_t*)As[st];
        const uint32_t* Bs32 = (const uint32_t*)Bs[st];
#pragma unroll
        for (int ks = 0; ks < 4; ks++) {
            int kk = ks * 8;
            uint32_t a[4][4], b[4][2];
#pragma unroll
            for (int mt = 0; mt < 4; mt++) {
                int r = wm + mt * 16 + g;
                a[mt][0] = As32[r * AS_STRIDE + kk + lk];
                a[mt][1] = As32[(r + 8) * AS_STRIDE + kk + lk];
                a[mt][2] = As32[r * AS_STRIDE + kk + lk + 4];
                a[mt][3] = As32[(r + 8) * AS_STRIDE + kk + lk + 4];
            }
#pragma unroll
            for (int nt = 0; nt < 4; nt++) {
                int c = wn + nt * 8 + g;
                b[nt][0] = Bs32[(kk + lk) * BS_STRIDE + c];
                b[nt][1] = Bs32[(kk + lk + 4) * BS_STRIDE + c];
            }
#pragma unroll
            for (int mt = 0; mt < 4; mt++)
#pragma unroll
                for (int nt = 0; nt < 4; nt++)
                    mma_1688(acc[mt][nt], a[mt], b[nt]);
        }
        __syncthreads();
    }

#pragma unroll
    for (int mt = 0; mt < 4; mt++) {
#pragma unroll
        for (int nt = 0; nt < 4; nt++) {
            int gCol = bN + wn + nt * 8 + 2 * lk;
            float bx = bias[gCol], by = bias[gCol + 1];
#pragma unroll
            for (int half = 0; half < 2; half++) {
                int gRow = bM + wm + mt * 16 + g + half * 8;
                float vx = acc[mt][nt][half * 2 + 0] + bx;
                float vy = acc[mt][nt][half * 2 + 1] + by;
                if (MODE == 0) {
                    *(float2*)(C + (size_t)gRow * Ncols + gCol) = make_float2(vx, vy);
                } else if (MODE == 1) {
                    int bb = gRow >> 10, n = gRow & 1023;
                    int h = gCol >> 6, d = gCol & 63;
                    *(float2*)(g_q + (((size_t)(bb * H_ + h)) * N_ + n) * D_ + d) =
                        make_float2(vx, vy);
                } else {
                    int bb = gRow >> 10, m = gRow & 1023;
                    int cc = gCol & 1023;
                    int h = cc >> 6, d = cc & 63;
                    float* dst = (gCol < DIM_) ? g_k : g_v;
                    *(float2*)(dst + (((size_t)(bb * H_ + h)) * M_ + m) * D_ + d) =
                        make_float2(vx, vy);
                }
            }
        }
    }
}

// ---------------------------------------------------------------------------
// Flash attention on mma.sync tf32.
// grid (8, 16, 4), 256 thr = 8 warps. S tile 128x128: warps 2x4 (wm 64, wn 32).
// O tile 128x64: warps 2x4 (wm 64, on 16). Online softmax on S fragments.
// Smem strides: A-side ≡ 4 mod 32 (68, 132), B-side ≡ 8 mod 32 (72).
// ---------------------------------------------------------------------------
constexpr int QS_S = 68, KS_S = 68, VS_S = 72, PS_S = 132;
constexpr int SMEM_ATTN =
    (128 * QS_S + 128 * KS_S + 128 * VS_S + 128 * PS_S + 512 + 512 + 512) * 4; // 180224

__global__ __launch_bounds__(256) void attn_mma_kernel() {
    extern __shared__ float sm[];
    float* Qs = sm;                       // [128][68]
    float* Ks = Qs + 128 * QS_S;          // [128][68]
    float* Vs = Ks + 128 * KS_S;          // [128][72]
    float* Ps = Vs + 128 * VS_S;          // [128][132]
    float* redmax = Ps + 128 * PS_S;      // [4][128]
    float* redsum = redmax + 512;         // [4][128]
    unsigned* Ms = (unsigned*)(redsum + 512); // [128][4]

    const uint32_t* Qs32 = (const uint32_t*)Qs;
    const uint32_t* Ks32 = (const uint32_t*)Ks;
    const uint32_t* Vs32 = (const uint32_t*)Vs;
    const uint32_t* Ps32 = (const uint32_t*)Ps;

    int tid = threadIdx.x;
    int wid = tid >> 5, lane = tid & 31;
    int g = lane >> 2, lk = lane & 3;
    int wm = (wid & 1) * 64;
    int wn = (wid >> 1) * 32;
    int on = (wid >> 1) * 16;
    int cg = wid >> 1;
    int n0 = blockIdx.x * 128;
    int h = blockIdx.y, b = blockIdx.z;

    const float* qp = g_q + (((size_t)(b * H_ + h)) * N_ + n0) * D_;
    const float* kp = g_k + ((size_t)(b * H_ + h)) * M_ * D_;
    const float* vp = g_v + ((size_t)(b * H_ + h)) * M_ * D_;
    const unsigned* mbp = g_mbits + ((size_t)(b * N_) + n0) * (M_ / 32);

    // Q tile: scaled + tf32 rounded
#pragma unroll
    for (int it = 0; it < 8; it++) {
        int i = tid + it * 256;
        int row = i >> 4, c = (i & 15) * 4;
        float4 f = *(const float4*)(qp + (size_t)row * D_ + c);
        Qs[row * QS_S + c + 0] = to_tf32(f.x * SCALE_);
        Qs[row * QS_S + c + 1] = to_tf32(f.y * SCALE_);
        Qs[row * QS_S + c + 2] = to_tf32(f.z * SCALE_);
        Qs[row * QS_S + c + 3] = to_tf32(f.w * SCALE_);
    }

    float acc_o[4][2][4];
#pragma unroll
    for (int mt = 0; mt < 4; mt++)
#pragma unroll
        for (int nt = 0; nt < 2; nt++)
#pragma unroll
            for (int i = 0; i < 4; i++) acc_o[mt][nt][i] = 0.f;
    float row_max[8], row_l[8];
#pragma unroll
    for (int i = 0; i < 8; i++) { row_max[i] = -1e30f; row_l[i] = 0.f; }

#pragma unroll 1
    for (int m0 = 0; m0 < M_; m0 += 128) {
        __syncthreads();   // prev tile fully consumed (incl. Qs stores on iter 0)
        // Load K (tf32), V (tf32), mask words
#pragma unroll
        for (int it = 0; it < 8; it++) {
            int i = tid + it * 256;
            int row = i >> 4, c = (i & 15) * 4;
            float4 f = *(const float4*)(kp + (size_t)(m0 + row) * D_ + c);
            Ks[row * KS_S + c + 0] = to_tf32(f.x);
            Ks[row * KS_S + c + 1] = to_tf32(f.y);
            Ks[row * KS_S + c + 2] = to_tf32(f.z);
            Ks[row * KS_S + c + 3] = to_tf32(f.w);
            float4 v = *(const float4*)(vp + (size_t)(m0 + row) * D_ + c);
            Vs[row * VS_S + c + 0] = to_tf32(v.x);
            Vs[row * VS_S + c + 1] = to_tf32(v.y);
            Vs[row * VS_S + c + 2] = to_tf32(v.z);
            Vs[row * VS_S + c + 3] = to_tf32(v.w);
        }
#pragma unroll
        for (int it = 0; it < 2; it++) {
            int i = tid + it * 256;
            int row = i >> 2, w = i & 3;
            Ms[row * 4 + w] = mbp[(size_t)row * (M_ / 32) + (m0 >> 5) + w];
        }
        __syncthreads();

        // ---- S = Q @ K^T ----
        float acc_s[4][4][4];
#pragma unroll
        for (int mt = 0; mt < 4; mt++)
#pragma unroll
            for (int nt = 0; nt < 4; nt++)
#pragma unroll
                for (int i = 0; i < 4; i++) acc_s[mt][nt][i] = 0.f;
#pragma unroll
        for (int ks = 0; ks < 8; ks++) {
            int kk = ks * 8;
            uint32_t a[4][4], bf[4][2];
#pragma unroll
            for (int mt = 0; mt < 4; mt++) {
                int r = wm + mt * 16 + g;
                a[mt][0] = Qs32[r * QS_S + kk + lk];
                a[mt][1] = Qs32[(r + 8) * QS_S + kk + lk];
                a[mt][2] = Qs32[r * QS_S + kk + lk + 4];
                a[mt][3] = Qs32[(r + 8) * QS_S + kk + lk + 4];
            }
#pragma unroll
            for (int nt = 0; nt < 4; nt++) {
                int c = wn + nt * 8 + g;
                bf[nt][0] = Ks32[c * KS_S + kk + lk];
                bf[nt][1] = Ks32[c * KS_S + kk + lk + 4];
            }
#pragma unroll
            for (int mt = 0; mt < 4; mt++)
#pragma unroll
                for (int nt = 0; nt < 4; nt++)
                    mma_1688(acc_s[mt][nt], a[mt], bf[nt]);
        }

        // ---- mask + per-warp row max ----
#pragma unroll
        for (int mt = 0; mt < 4; mt++) {
#pragma unroll
            for (int half = 0; half < 2; half++) {
                int rloc = wm + mt * 16 + g + half * 8;
                unsigned mw = Ms[rloc * 4 + (wn >> 5)];
                float mx = -1e30f;
#pragma unroll
                for (int nt = 0; nt < 4; nt++) {
                    int bit = nt * 8 + 2 * lk;
                    float s0 = acc_s[mt][nt][half * 2 + 0];
                    float s1 = acc_s[mt][nt][half * 2 + 1];
                    if (!((mw >> bit) & 1u)) s0 = -INFINITY;
                    if (!((mw >> (bit + 1)) & 1u)) s1 = -INFINITY;
                    acc_s[mt][nt][half * 2 + 0] = s0;
                    acc_s[mt][nt][half * 2 + 1] = s1;
                    mx = fmaxf(mx, fmaxf(s0, s1));
                }
                mx = fmaxf(mx, __shfl_xor_sync(0xffffffffu, mx, 1));
                mx = fmaxf(mx, __shfl_xor_sync(0xffffffffu, mx, 2));
                if (lk == 0) redmax[cg * 128 + rloc] = mx;
            }
        }
        __syncthreads();

        // ---- finalize max, compute P (tf32), partial sums ----
        float corr_s[8];
#pragma unroll
        for (int mt = 0; mt < 4; mt++) {
#pragma unroll
            for (int half = 0; half < 2; half++) {
                int ri = mt * 2 + half;
                int rloc = wm + mt * 16 + g + half * 8;
                float mx = fmaxf(fmaxf(redmax[rloc], redmax[128 + rloc]),
                                 fmaxf(redmax[256 + rloc], redmax[384 + rloc]));
                float nm = fmaxf(fmaxf(row_max[ri], mx), -1e30f);
                float corr = __expf(row_max[ri] - nm);
                row_max[ri] = nm;
                corr_s[ri] = corr;
                float lsum = 0.f;
#pragma unroll
                for (int nt = 0; nt < 4; nt++) {
                    float p0 = to_tf32(__expf(acc_s[mt][nt][half * 2 + 0] - nm));
                    float p1 = to_tf32(__expf(acc_s[mt][nt][half * 2 + 1] - nm));
                    lsum += p0 + p1;
                    *(float2*)&Ps[rloc * PS_S + wn + nt * 8 + 2 * lk] =
                        make_float2(p0, p1);
                }
                lsum += __shfl_xor_sync(0xffffffffu, lsum, 1);
                lsum += __shfl_xor_sync(0xffffffffu, lsum, 2);
                if (lk == 0) redsum[cg * 128 + rloc] = lsum;
                // rescale O accumulators for these rows
#pragma unroll
                for (int nt = 0; nt < 2; nt++) {
                    acc_o[mt][nt][half * 2 + 0] *= corr;
                    acc_o[mt][nt][half * 2 + 1] *= corr;
                }
            }
        }
        __syncthreads();

#pragma unroll
        for (int mt = 0; mt < 4; mt++) {
#pragma unroll
            for (int half = 0; half < 2; half++) {
                int ri = mt * 2 + half;
                int rloc = wm + mt * 16 + g + half * 8;
                float ts = (redsum[rloc] + redsum[128 + rloc]) +
                           (redsum[256 + rloc] + redsum[384 + rloc]);
                row_l[ri] = row_l[ri] * corr_s[ri] + ts;
            }
        }

        // ---- O += P @ V ----
#pragma unroll
        for (int ks = 0; ks < 16; ks++) {
            int kk = ks * 8;
            uint32_t a[4][4], bf[2][2];
#pragma unroll
            for (int mt = 0; mt < 4; mt++) {
                int r = wm + mt * 16 + g;
                a[mt][0] = Ps32[r * PS_S + kk + lk];
                a[mt][1] = Ps32[(r + 8) * PS_S + kk + lk];
                a[mt][2] = Ps32[r * PS_S + kk + lk + 4];
                a[mt][3] = Ps32[(r + 8) * PS_S + kk + lk + 4];
            }
#pragma unroll
            for (int nt = 0; nt < 2; nt++) {
                int c = on + nt * 8 + g;
                bf[nt][0] = Vs32[(kk + lk) * VS_S + c];
                bf[nt][1] = Vs32[(kk + lk + 4) * VS_S + c];
            }
#pragma unroll
            for (int mt = 0; mt < 4; mt++)
#pragma unroll
                for (int nt = 0; nt < 2; nt++)
                    mma_1688(acc_o[mt][nt], a[mt], bf[nt]);
        }
    }

    // Epilogue: normalize, store to g_ao [b,n,h*d]
#pragma unroll
    for (int mt = 0; mt < 4; mt++) {
#pragma unroll
        for (int half = 0; half < 2; half++) {
            int ri = mt * 2 + half;
            int rloc = wm + mt * 16 + g + half * 8;
            float inv = 1.0f / row_l[ri];
#pragma unroll
            for (int nt = 0; nt < 2; nt++) {
                int c = on + nt * 8 + 2 * lk;
                float2 o = make_float2(acc_o[mt][nt][half * 2 + 0] * inv,
                                       acc_o[mt][nt][half * 2 + 1] * inv);
                *(float2*)(g_ao + ((size_t)(b * N_) + n0 + rloc) * DIM_ +
                           h * D_ + c) = o;
            }
        }
    }
}

// ---------------------------------------------------------------------------
// Launch
// ---------------------------------------------------------------------------
extern "C" void kernel_launch(void* const* d_in, const int* in_sizes, int n_in,
                              void* d_out, int out_size) {
    const float* x   = (const float*)d_in[0];
    const float* ctx = (const float*)d_in[1];
    const int*   msk = (const int*)d_in[2];
    const float* Wq  = (const float*)d_in[3];
    const float* bq  = (const float*)d_in[4];
    const float* Wkv = (const float*)d_in[5];
    const float* bkv = (const float*)d_in[6];
    const float* Wp  = (const float*)d_in[7];
    const float* bp  = (const float*)d_in[8];
    float* out = (float*)d_out;

    cudaFuncSetAttribute(attn_mma_kernel,
                         cudaFuncAttributeMaxDynamicSharedMemorySize, SMEM_ATTN);
    cudaFuncSetAttribute(mma_gemm<0>,
                         cudaFuncAttributeMaxDynamicSharedMemorySize, SMEM_GEMM);
    cudaFuncSetAttribute(mma_gemm<1>,
                         cudaFuncAttributeMaxDynamicSharedMemorySize, SMEM_GEMM);
    cudaFuncSetAttribute(mma_gemm<2>,
                         cudaFuncAttributeMaxDynamicSharedMemorySize, SMEM_GEMM);

    pack_mask_kernel<<<(B_ * N_) / 8, 256>>>(msk);
    mma_gemm<1><<<dim3(DIM_ / 128, B_ * N_ / 128), 256, SMEM_GEMM>>>(
        x, Wq, bq, nullptr, B_ * N_, DIM_, DIM_);
    mma_gemm<2><<<dim3(2 * DIM_ / 128, B_ * M_ / 128), 256, SMEM_GEMM>>>(
        ctx, Wkv, bkv, nullptr, B_ * M_, 2 * DIM_, DIM_);
    attn_mma_kernel<<<dim3(N_ / 128, H_, B_), 256, SMEM_ATTN>>>();
    mma_gemm<0><<<dim3(DIM_ / 128, B_ * N_ / 128), 256, SMEM_GEMM>>>(
        nullptr, Wp, bp, out, B_ * N_, DIM_, DIM_);
}

// round 12
// speedup vs baseline: 3.6738x; 1.4744x over previous
#include <cuda_runtime.h>
#include <cstdint>

// Problem constants
constexpr int B_ = 4, H_ = 16, N_ = 1024, M_ = 1024, D_ = 64, DIM_ = 1024;
constexpr float SCALE_ = 0.125f;   // 64^-0.5

// Scratch (device globals — no allocation allowed)
__device__ float g_q[(size_t)B_ * H_ * N_ * D_];        // [b,h,n,d]
__device__ float g_k[(size_t)B_ * H_ * M_ * D_];        // [b,h,m,d]
__device__ float g_v[(size_t)B_ * H_ * M_ * D_];        // [b,h,m,d]
__device__ float g_ao[(size_t)B_ * N_ * DIM_];          // [b,n,h*d] (tf32-rounded)
__device__ unsigned g_mbits[(size_t)B_ * N_ * (M_ / 32)]; // packed mask bits
// tf32 pre-rounded copies of inputs/weights
__device__ float g_x32[(size_t)B_ * N_ * DIM_];
__device__ float g_c32[(size_t)B_ * M_ * DIM_];
__device__ float g_wq32[(size_t)DIM_ * DIM_];
__device__ float g_wkv32[(size_t)DIM_ * 2 * DIM_];
__device__ float g_wp32[(size_t)DIM_ * DIM_];

// ---------------------------------------------------------------------------
// Helpers
// ---------------------------------------------------------------------------
__device__ __forceinline__ float to_tf32(float x) {
    float r; asm("cvt.rna.tf32.f32 %0, %1;" : "=f"(r) : "f"(x)); return r;
}
__device__ __forceinline__ void mma_1688(float* d, const uint32_t* a, const uint32_t* b) {
    asm volatile(
        "mma.sync.aligned.m16n8k8.row.col.f32.tf32.tf32.f32 "
        "{%0,%1,%2,%3}, {%4,%5,%6,%7}, {%8,%9}, {%0,%1,%2,%3};"
        : "+f"(d[0]), "+f"(d[1]), "+f"(d[2]), "+f"(d[3])
        : "r"(a[0]), "r"(a[1]), "r"(a[2]), "r"(a[3]), "r"(b[0]), "r"(b[1]));
}
__device__ __forceinline__ void cp16(void* smem_dst, const void* gsrc) {
    uint32_t s = (uint32_t)__cvta_generic_to_shared(smem_dst);
    asm volatile("cp.async.cg.shared.global [%0], [%1], 16;" :: "r"(s), "l"(gsrc));
}
#define CP_COMMIT() asm volatile("cp.async.commit_group;" ::: "memory")
#define CP_WAIT1()  asm volatile("cp.async.wait_group 1;" ::: "memory")

// ---------------------------------------------------------------------------
// tf32 pre-round: dst[i] = round_rna_tf32(src[i])
// ---------------------------------------------------------------------------
template <int SEL>
__global__ __launch_bounds__(256) void tf32_round_kernel(const float* __restrict__ src) {
    float* dst = (SEL == 0) ? g_x32 : (SEL == 1) ? g_c32 :
                 (SEL == 2) ? g_wq32 : (SEL == 3) ? g_wkv32 : g_wp32;
    size_t i = ((size_t)blockIdx.x * 256 + threadIdx.x) * 4;
    float4 v = *(const float4*)(src + i);
    v.x = to_tf32(v.x); v.y = to_tf32(v.y);
    v.z = to_tf32(v.z); v.w = to_tf32(v.w);
    *(float4*)(dst + i) = v;
}

// ---------------------------------------------------------------------------
// Pack int32 mask [b,n,1024] into bitmask words [b,n,32]
// ---------------------------------------------------------------------------
__global__ __launch_bounds__(256) void pack_mask_kernel(const int* __restrict__ mask) {
    int lane = threadIdx.x & 31;
    int row = blockIdx.x * 8 + (threadIdx.x >> 5);
    const int* mrow = mask + (size_t)row * M_;
    unsigned* brow = g_mbits + (size_t)row * (M_ / 32);
#pragma unroll 4
    for (int w = 0; w < M_ / 32; w++) {
        int v = mrow[w * 32 + lane];
        unsigned bits = __ballot_sync(0xffffffffu, v != 0);
        if (lane == 0) brow[w] = bits;
    }
}

// ---------------------------------------------------------------------------
// HMMA tf32 GEMM v2: cp.async 3-stage pipeline, 1 sync per K-chunk.
// C[128x128] = A[M,K] @ W[K,N] + bias. Inputs pre-rounded to tf32.
// MODE 0: g_ao @ g_wp32 -> C   MODE 1: g_x32 @ g_wq32 -> Q scatter
// MODE 2: g_c32 @ g_wkv32 -> K/V scatter
// ---------------------------------------------------------------------------
constexpr int AS_STRIDE = 36;                  // words per A smem row
constexpr int BS_STRIDE = 136;                 // words per B smem row
constexpr int A_STAGE = 128 * AS_STRIDE;       // words
constexpr int B_STAGE = 32 * BS_STRIDE;        // words
constexpr int SMEM_GEMM = 3 * (A_STAGE + B_STAGE) * 4;  // 107520 B

template <int MODE>
__global__ __launch_bounds__(256, 2) void mma_gemm(
    const float* __restrict__ bias, float* __restrict__ C, int Ncols, int K)
{
    extern __shared__ float smem[];
    float* As[3] = { smem, smem + A_STAGE, smem + 2 * A_STAGE };
    float* Bs[3] = { smem + 3 * A_STAGE, smem + 3 * A_STAGE + B_STAGE,
                     smem + 3 * A_STAGE + 2 * B_STAGE };

    const float* A = (MODE == 0) ? g_ao : (MODE == 1) ? g_x32 : g_c32;
    const float* W = (MODE == 0) ? g_wp32 : (MODE == 1) ? g_wq32 : g_wkv32;

    int tid = threadIdx.x;
    int wid = tid >> 5, lane = tid & 31;
    int g = lane >> 2, lk = lane & 3;
    int wm = (wid & 1) * 64, wn = (wid >> 1) * 32;
    int bM = blockIdx.y * 128, bN = blockIdx.x * 128;

    const float* Ab = A + (size_t)bM * K;
    const float* Wb = W + bN;

    // loader: 4 x 16B for A (128x32) + 4 x 16B for B (32x128) per thread
    auto issue = [&](int ch) {
        int k0 = ch * 32;
        int st = ch % 3;
#pragma unroll
        for (int it = 0; it < 4; it++) {
            int i = tid + it * 256;
            int row = i >> 3, j = i & 7;
            cp16(&As[st][row * AS_STRIDE + j * 4], Ab + (size_t)row * K + k0 + j * 4);
            int brow = i >> 5, bcol = (i & 31) * 4;
            cp16(&Bs[st][brow * BS_STRIDE + bcol],
                 Wb + (size_t)(k0 + brow) * Ncols + bcol);
        }
    };

    float acc[4][4][4];
#pragma unroll
    for (int mt = 0; mt < 4; mt++)
#pragma unroll
        for (int nt = 0; nt < 4; nt++)
#pragma unroll
            for (int i = 0; i < 4; i++) acc[mt][nt][i] = 0.f;

    issue(0); CP_COMMIT();
    issue(1); CP_COMMIT();

    const int NCH = K / 32;
#pragma unroll 1
    for (int ch = 0; ch < NCH; ch++) {
        CP_WAIT1();
        __syncthreads();
        if (ch + 2 < NCH) issue(ch + 2);
        CP_COMMIT();   // empty commits at tail keep wait_group semantics exact

        int st = ch % 3;
        const uint32_t* As32 = (const uint32_t*)As[st];
        const uint32_t* Bs32 = (const uint32_t*)Bs[st];
#pragma unroll
        for (int ks = 0; ks < 4; ks++) {
            int kk = ks * 8;
            uint32_t a[4][4], b[4][2];
#pragma unroll
            for (int mt = 0; mt < 4; mt++) {
                int r = wm + mt * 16 + g;
                a[mt][0] = As32[r * AS_STRIDE + kk + lk];
                a[mt][1] = As32[(r + 8) * AS_STRIDE + kk + lk];
                a[mt][2] = As32[r * AS_STRIDE + kk + lk + 4];
                a[mt][3] = As32[(r + 8) * AS_STRIDE + kk + lk + 4];
            }
#pragma unroll
            for (int nt = 0; nt < 4; nt++) {
                int c = wn + nt * 8 + g;
                b[nt][0] = Bs32[(kk + lk) * BS_STRIDE + c];
                b[nt][1] = Bs32[(kk + lk + 4) * BS_STRIDE + c];
            }
#pragma unroll
            for (int mt = 0; mt < 4; mt++)
#pragma unroll
                for (int nt = 0; nt < 4; nt++)
                    mma_1688(acc[mt][nt], a[mt], b[nt]);
        }
    }

    // Epilogue
#pragma unroll
    for (int mt = 0; mt < 4; mt++) {
#pragma unroll
        for (int nt = 0; nt < 4; nt++) {
            int gCol = bN + wn + nt * 8 + 2 * lk;
            float bx = bias[gCol], by = bias[gCol + 1];
#pragma unroll
            for (int half = 0; half < 2; half++) {
                int gRow = bM + wm + mt * 16 + g + half * 8;
                float vx = acc[mt][nt][half * 2 + 0] + bx;
                float vy = acc[mt][nt][half * 2 + 1] + by;
                if (MODE == 0) {
                    *(float2*)(C + (size_t)gRow * Ncols + gCol) = make_float2(vx, vy);
                } else if (MODE == 1) {
                    int bb = gRow >> 10, n = gRow & 1023;
                    int h = gCol >> 6, d = gCol & 63;
                    *(float2*)(g_q + (((size_t)(bb * H_ + h)) * N_ + n) * D_ + d) =
                        make_float2(vx, vy);
                } else {
                    int bb = gRow >> 10, m = gRow & 1023;
                    int cc = gCol & 1023;
                    int h = cc >> 6, d = cc & 63;
                    float* dst = (gCol < DIM_) ? g_k : g_v;
                    *(float2*)(dst + (((size_t)(bb * H_ + h)) * M_ + m) * D_ + d) =
                        make_float2(vx, vy);
                }
            }
        }
    }
}

// ---------------------------------------------------------------------------
// Flash attention on mma.sync tf32 (unchanged from R9 except tf32-rounded
// epilogue store into g_ao so the out-projection can cp.async it directly).
// ---------------------------------------------------------------------------
constexpr int QS_S = 68, KS_S = 68, VS_S = 72, PS_S = 132;
constexpr int SMEM_ATTN =
    (128 * QS_S + 128 * KS_S + 128 * VS_S + 128 * PS_S + 512 + 512 + 512) * 4;

__global__ __launch_bounds__(256) void attn_mma_kernel() {
    extern __shared__ float sm[];
    float* Qs = sm;
    float* Ks = Qs + 128 * QS_S;
    float* Vs = Ks + 128 * KS_S;
    float* Ps = Vs + 128 * VS_S;
    float* redmax = Ps + 128 * PS_S;
    float* redsum = redmax + 512;
    unsigned* Ms = (unsigned*)(redsum + 512);

    const uint32_t* Qs32 = (const uint32_t*)Qs;
    const uint32_t* Ks32 = (const uint32_t*)Ks;
    const uint32_t* Vs32 = (const uint32_t*)Vs;
    const uint32_t* Ps32 = (const uint32_t*)Ps;

    int tid = threadIdx.x;
    int wid = tid >> 5, lane = tid & 31;
    int g = lane >> 2, lk = lane & 3;
    int wm = (wid & 1) * 64;
    int wn = (wid >> 1) * 32;
    int on = (wid >> 1) * 16;
    int cg = wid >> 1;
    int n0 = blockIdx.x * 128;
    int h = blockIdx.y, b = blockIdx.z;

    const float* qp = g_q + (((size_t)(b * H_ + h)) * N_ + n0) * D_;
    const float* kp = g_k + ((size_t)(b * H_ + h)) * M_ * D_;
    const float* vp = g_v + ((size_t)(b * H_ + h)) * M_ * D_;
    const unsigned* mbp = g_mbits + ((size_t)(b * N_) + n0) * (M_ / 32);

#pragma unroll
    for (int it = 0; it < 8; it++) {
        int i = tid + it * 256;
        int row = i >> 4, c = (i & 15) * 4;
        float4 f = *(const float4*)(qp + (size_t)row * D_ + c);
        Qs[row * QS_S + c + 0] = to_tf32(f.x * SCALE_);
        Qs[row * QS_S + c + 1] = to_tf32(f.y * SCALE_);
        Qs[row * QS_S + c + 2] = to_tf32(f.z * SCALE_);
        Qs[row * QS_S + c + 3] = to_tf32(f.w * SCALE_);
    }

    float acc_o[4][2][4];
#pragma unroll
    for (int mt = 0; mt < 4; mt++)
#pragma unroll
        for (int nt = 0; nt < 2; nt++)
#pragma unroll
            for (int i = 0; i < 4; i++) acc_o[mt][nt][i] = 0.f;
    float row_max[8], row_l[8];
#pragma unroll
    for (int i = 0; i < 8; i++) { row_max[i] = -1e30f; row_l[i] = 0.f; }

#pragma unroll 1
    for (int m0 = 0; m0 < M_; m0 += 128) {
        __syncthreads();
#pragma unroll
        for (int it = 0; it < 8; it++) {
            int i = tid + it * 256;
            int row = i >> 4, c = (i & 15) * 4;
            float4 f = *(const float4*)(kp + (size_t)(m0 + row) * D_ + c);
            Ks[row * KS_S + c + 0] = to_tf32(f.x);
            Ks[row * KS_S + c + 1] = to_tf32(f.y);
            Ks[row * KS_S + c + 2] = to_tf32(f.z);
            Ks[row * KS_S + c + 3] = to_tf32(f.w);
            float4 v = *(const float4*)(vp + (size_t)(m0 + row) * D_ + c);
            Vs[row * VS_S + c + 0] = to_tf32(v.x);
            Vs[row * VS_S + c + 1] = to_tf32(v.y);
            Vs[row * VS_S + c + 2] = to_tf32(v.z);
            Vs[row * VS_S + c + 3] = to_tf32(v.w);
        }
#pragma unroll
        for (int it = 0; it < 2; it++) {
            int i = tid + it * 256;
            int row = i >> 2, w = i & 3;
            Ms[row * 4 + w] = mbp[(size_t)row * (M_ / 32) + (m0 >> 5) + w];
        }
        __syncthreads();

        float acc_s[4][4][4];
#pragma unroll
        for (int mt = 0; mt < 4; mt++)
#pragma unroll
            for (int nt = 0; nt < 4; nt++)
#pragma unroll
                for (int i = 0; i < 4; i++) acc_s[mt][nt][i] = 0.f;
#pragma unroll
        for (int ks = 0; ks < 8; ks++) {
            int kk = ks * 8;
            uint32_t a[4][4], bf[4][2];
#pragma unroll
            for (int mt = 0; mt < 4; mt++) {
                int r = wm + mt * 16 + g;
                a[mt][0] = Qs32[r * QS_S + kk + lk];
                a[mt][1] = Qs32[(r + 8) * QS_S + kk + lk];
                a[mt][2] = Qs32[r * QS_S + kk + lk + 4];
                a[mt][3] = Qs32[(r + 8) * QS_S + kk + lk + 4];
            }
#pragma unroll
            for (int nt = 0; nt < 4; nt++) {
                int c = wn + nt * 8 + g;
                bf[nt][0] = Ks32[c * KS_S + kk + lk];
                bf[nt][1] = Ks32[c * KS_S + kk + lk + 4];
            }
#pragma unroll
            for (int mt = 0; mt < 4; mt++)
#pragma unroll
                for (int nt = 0; nt < 4; nt++)
                    mma_1688(acc_s[mt][nt], a[mt], bf[nt]);
        }

#pragma unroll
        for (int mt = 0; mt < 4; mt++) {
#pragma unroll
            for (int half = 0; half < 2; half++) {
                int rloc = wm + mt * 16 + g + half * 8;
                unsigned mw = Ms[rloc * 4 + (wn >> 5)];
                float mx = -1e30f;
#pragma unroll
                for (int nt = 0; nt < 4; nt++) {
                    int bit = nt * 8 + 2 * lk;
                    float s0 = acc_s[mt][nt][half * 2 + 0];
                    float s1 = acc_s[mt][nt][half * 2 + 1];
                    if (!((mw >> bit) & 1u)) s0 = -INFINITY;
                    if (!((mw >> (bit + 1)) & 1u)) s1 = -INFINITY;
                    acc_s[mt][nt][half * 2 + 0] = s0;
                    acc_s[mt][nt][half * 2 + 1] = s1;
                    mx = fmaxf(mx, fmaxf(s0, s1));
                }
                mx = fmaxf(mx, __shfl_xor_sync(0xffffffffu, mx, 1));
                mx = fmaxf(mx, __shfl_xor_sync(0xffffffffu, mx, 2));
                if (lk == 0) redmax[cg * 128 + rloc] = mx;
            }
        }
        __syncthreads();

        float corr_s[8];
#pragma unroll
        for (int mt = 0; mt < 4; mt++) {
#pragma unroll
            for (int half = 0; half < 2; half++) {
                int ri = mt * 2 + half;
                int rloc = wm + mt * 16 + g + half * 8;
                float mx = fmaxf(fmaxf(redmax[rloc], redmax[128 + rloc]),
                                 fmaxf(redmax[256 + rloc], redmax[384 + rloc]));
                float nm = fmaxf(fmaxf(row_max[ri], mx), -1e30f);
                float corr = __expf(row_max[ri] - nm);
                row_max[ri] = nm;
                corr_s[ri] = corr;
                float lsum = 0.f;
#pragma unroll
                for (int nt = 0; nt < 4; nt++) {
                    float p0 = to_tf32(__expf(acc_s[mt][nt][half * 2 + 0] - nm));
                    float p1 = to_tf32(__expf(acc_s[mt][nt][half * 2 + 1] - nm));
                    lsum += p0 + p1;
                    *(float2*)&Ps[rloc * PS_S + wn + nt * 8 + 2 * lk] =
                        make_float2(p0, p1);
                }
                lsum += __shfl_xor_sync(0xffffffffu, lsum, 1);
                lsum += __shfl_xor_sync(0xffffffffu, lsum, 2);
                if (lk == 0) redsum[cg * 128 + rloc] = lsum;
#pragma unroll
                for (int nt = 0; nt < 2; nt++) {
                    acc_o[mt][nt][half * 2 + 0] *= corr;
                    acc_o[mt][nt][half * 2 + 1] *= corr;
                }
            }
        }
        __syncthreads();

#pragma unroll
        for (int mt = 0; mt < 4; mt++) {
#pragma unroll
            for (int half = 0; half < 2; half++) {
                int ri = mt * 2 + half;
                int rloc = wm + mt * 16 + g + half * 8;
                float ts = (redsum[rloc] + redsum[128 + rloc]) +
                           (redsum[256 + rloc] + redsum[384 + rloc]);
                row_l[ri] = row_l[ri] * corr_s[ri] + ts;
            }
        }

#pragma unroll
        for (int ks = 0; ks < 16; ks++) {
            int kk = ks * 8;
            uint32_t a[4][4], bf[2][2];
#pragma unroll
            for (int mt = 0; mt < 4; mt++) {
                int r = wm + mt * 16 + g;
                a[mt][0] = Ps32[r * PS_S + kk + lk];
                a[mt][1] = Ps32[(r + 8) * PS_S + kk + lk];
                a[mt][2] = Ps32[r * PS_S + kk + lk + 4];
                a[mt][3] = Ps32[(r + 8) * PS_S + kk + lk + 4];
            }
#pragma unroll
            for (int nt = 0; nt < 2; nt++) {
                int c = on + nt * 8 + g;
                bf[nt][0] = Vs32[(kk + lk) * VS_S + c];
                bf[nt][1] = Vs32[(kk + lk + 4) * VS_S + c];
            }
#pragma unroll
            for (int mt = 0; mt < 4; mt++)
#pragma unroll
                for (int nt = 0; nt < 2; nt++)
                    mma_1688(acc_o[mt][nt], a[mt], bf[nt]);
        }
    }

    // Epilogue: normalize + tf32-round (out-proj consumes via cp.async)
#pragma unroll
    for (int mt = 0; mt < 4; mt++) {
#pragma unroll
        for (int half = 0; half < 2; half++) {
            int ri = mt * 2 + half;
            int rloc = wm + mt * 16 + g + half * 8;
            float inv = 1.0f / row_l[ri];
#pragma unroll
            for (int nt = 0; nt < 2; nt++) {
                int c = on + nt * 8 + 2 * lk;
                float2 o = make_float2(to_tf32(acc_o[mt][nt][half * 2 + 0] * inv),
                                       to_tf32(acc_o[mt][nt][half * 2 + 1] * inv));
                *(float2*)(g_ao + ((size_t)(b * N_) + n0 + rloc) * DIM_ +
                           h * D_ + c) = o;
            }
        }
    }
}

// ---------------------------------------------------------------------------
// Launch
// ---------------------------------------------------------------------------
extern "C" void kernel_launch(void* const* d_in, const int* in_sizes, int n_in,
                              void* d_out, int out_size) {
    const float* x   = (const float*)d_in[0];
    const float* ctx = (const float*)d_in[1];
    const int*   msk = (const int*)d_in[2];
    const float* Wq  = (const float*)d_in[3];
    const float* bq  = (const float*)d_in[4];
    const float* Wkv = (const float*)d_in[5];
    const float* bkv = (const float*)d_in[6];
    const float* Wp  = (const float*)d_in[7];
    const float* bp  = (const float*)d_in[8];
    float* out = (float*)d_out;

    cudaFuncSetAttribute(attn_mma_kernel,
                         cudaFuncAttributeMaxDynamicSharedMemorySize, SMEM_ATTN);
    cudaFuncSetAttribute(mma_gemm<0>,
                         cudaFuncAttributeMaxDynamicSharedMemorySize, SMEM_GEMM);
    cudaFuncSetAttribute(mma_gemm<1>,
                         cudaFuncAttributeMaxDynamicSharedMemorySize, SMEM_GEMM);
    cudaFuncSetAttribute(mma_gemm<2>,
                         cudaFuncAttributeMaxDynamicSharedMemorySize, SMEM_GEMM);

    pack_mask_kernel<<<(B_ * N_) / 8, 256>>>(msk);
    tf32_round_kernel<0><<<(B_ * N_ * DIM_) / 1024, 256>>>(x);
    tf32_round_kernel<1><<<(B_ * M_ * DIM_) / 1024, 256>>>(ctx);
    tf32_round_kernel<2><<<(DIM_ * DIM_) / 1024, 256>>>(Wq);
    tf32_round_kernel<3><<<(DIM_ * 2 * DIM_) / 1024, 256>>>(Wkv);
    tf32_round_kernel<4><<<(DIM_ * DIM_) / 1024, 256>>>(Wp);

    mma_gemm<1><<<dim3(DIM_ / 128, B_ * N_ / 128), 256, SMEM_GEMM>>>(
        bq, nullptr, DIM_, DIM_);
    mma_gemm<2><<<dim3(2 * DIM_ / 128, B_ * M_ / 128), 256, SMEM_GEMM>>>(
        bkv, nullptr, 2 * DIM_, DIM_);
    attn_mma_kernel<<<dim3(N_ / 128, H_, B_), 256, SMEM_ATTN>>>();
    mma_gemm<0><<<dim3(DIM_ / 128, B_ * N_ / 128), 256, SMEM_GEMM>>>(
        bp, out, DIM_, DIM_);
}

// round 13
// speedup vs baseline: 3.8227x; 1.0405x over previous
#include <cuda_runtime.h>
#include <cstdint>

// Problem constants
constexpr int B_ = 4, H_ = 16, N_ = 1024, M_ = 1024, D_ = 64, DIM_ = 1024;
constexpr float SCALE_ = 0.125f;   // 64^-0.5

// Scratch (device globals — no allocation allowed)
__device__ float g_q[(size_t)B_ * H_ * N_ * D_];        // [b,h,n,d] tf32(q*SCALE)
__device__ float g_k[(size_t)B_ * H_ * M_ * D_];        // [b,h,m,d] tf32
__device__ float g_v[(size_t)B_ * H_ * M_ * D_];        // [b,h,m,d] tf32
__device__ float g_ao[(size_t)B_ * N_ * DIM_];          // [b,n,h*d] tf32
__device__ unsigned g_mbits[(size_t)B_ * N_ * (M_ / 32)]; // packed mask bits
// tf32 pre-rounded copies of inputs/weights
__device__ float g_x32[(size_t)B_ * N_ * DIM_];
__device__ float g_c32[(size_t)B_ * M_ * DIM_];
__device__ float g_wq32[(size_t)DIM_ * DIM_];
__device__ float g_wkv32[(size_t)DIM_ * 2 * DIM_];
__device__ float g_wp32[(size_t)DIM_ * DIM_];

// ---------------------------------------------------------------------------
// Helpers
// ---------------------------------------------------------------------------
__device__ __forceinline__ float to_tf32(float x) {
    float r; asm("cvt.rna.tf32.f32 %0, %1;" : "=f"(r) : "f"(x)); return r;
}
__device__ __forceinline__ void mma_1688(float* d, const uint32_t* a, const uint32_t* b) {
    asm volatile(
        "mma.sync.aligned.m16n8k8.row.col.f32.tf32.tf32.f32 "
        "{%0,%1,%2,%3}, {%4,%5,%6,%7}, {%8,%9}, {%0,%1,%2,%3};"
        : "+f"(d[0]), "+f"(d[1]), "+f"(d[2]), "+f"(d[3])
        : "r"(a[0]), "r"(a[1]), "r"(a[2]), "r"(a[3]), "r"(b[0]), "r"(b[1]));
}
__device__ __forceinline__ void cp16(void* smem_dst, const void* gsrc) {
    uint32_t s = (uint32_t)__cvta_generic_to_shared(smem_dst);
    asm volatile("cp.async.cg.shared.global [%0], [%1], 16;" :: "r"(s), "l"(gsrc));
}
__device__ __forceinline__ void cp8(void* smem_dst, const void* gsrc) {
    uint32_t s = (uint32_t)__cvta_generic_to_shared(smem_dst);
    asm volatile("cp.async.ca.shared.global [%0], [%1], 8;" :: "r"(s), "l"(gsrc));
}
#define CP_COMMIT() asm volatile("cp.async.commit_group;" ::: "memory")
#define CP_WAIT1()  asm volatile("cp.async.wait_group 1;" ::: "memory")
#define CP_WAIT0()  asm volatile("cp.async.wait_group 0;" ::: "memory")

// ---------------------------------------------------------------------------
// Fused tf32 pre-round of all 5 tensors (segment lookup on flat float4 index)
// ---------------------------------------------------------------------------
__global__ __launch_bounds__(256) void tf32_round_all(
    const float* __restrict__ x, const float* __restrict__ ctx,
    const float* __restrict__ Wq, const float* __restrict__ Wkv,
    const float* __restrict__ Wp)
{
    size_t i = (size_t)blockIdx.x * 256 + threadIdx.x;   // float4 index
    const float* src; float* dst; size_t off;
    if (i < 1048576)      { src = x;   dst = g_x32;  off = i; }
    else if (i < 2097152) { src = ctx; dst = g_c32;  off = i - 1048576; }
    else if (i < 2359296) { src = Wq;  dst = g_wq32; off = i - 2097152; }
    else if (i < 2883584) { src = Wkv; dst = g_wkv32; off = i - 2359296; }
    else                  { src = Wp;  dst = g_wp32; off = i - 2883584; }
    float4 v = *(const float4*)(src + off * 4);
    v.x = to_tf32(v.x); v.y = to_tf32(v.y);
    v.z = to_tf32(v.z); v.w = to_tf32(v.w);
    *(float4*)(dst + off * 4) = v;
}

// ---------------------------------------------------------------------------
// Pack int32 mask [b,n,1024] into bitmask words [b,n,32]
// ---------------------------------------------------------------------------
__global__ __launch_bounds__(256) void pack_mask_kernel(const int* __restrict__ mask) {
    int lane = threadIdx.x & 31;
    int row = blockIdx.x * 8 + (threadIdx.x >> 5);
    const int* mrow = mask + (size_t)row * M_;
    unsigned* brow = g_mbits + (size_t)row * (M_ / 32);
#pragma unroll 4
    for (int w = 0; w < M_ / 32; w++) {
        int v = mrow[w * 32 + lane];
        unsigned bits = __ballot_sync(0xffffffffu, v != 0);
        if (lane == 0) brow[w] = bits;
    }
}

// ---------------------------------------------------------------------------
// GEMM core (shared by both GEMM kernels): 128x128 tile, cp.async 3-stage
// ---------------------------------------------------------------------------
constexpr int AS_STRIDE = 36;
constexpr int BS_STRIDE = 136;
constexpr int A_STAGE = 128 * AS_STRIDE;
constexpr int B_STAGE = 32 * BS_STRIDE;
constexpr int SMEM_GEMM = 3 * (A_STAGE + B_STAGE) * 4;  // 107520 B

struct GemmCore {
    float acc[4][4][4];
    __device__ __forceinline__ void run(
        float* smem, const float* Ab, const float* Wb, int Ncols, int K,
        int tid, int g, int lk, int wm, int wn)
    {
        float* As[3] = { smem, smem + A_STAGE, smem + 2 * A_STAGE };
        float* Bs[3] = { smem + 3 * A_STAGE, smem + 3 * A_STAGE + B_STAGE,
                         smem + 3 * A_STAGE + 2 * B_STAGE };
#pragma unroll
        for (int mt = 0; mt < 4; mt++)
#pragma unroll
            for (int nt = 0; nt < 4; nt++)
#pragma unroll
                for (int i = 0; i < 4; i++) acc[mt][nt][i] = 0.f;

        auto issue = [&](int ch) {
            int k0 = ch * 32, st = ch % 3;
#pragma unroll
            for (int it = 0; it < 4; it++) {
                int i = tid + it * 256;
                int row = i >> 3, j = i & 7;
                cp16(&As[st][row * AS_STRIDE + j * 4],
                     Ab + (size_t)row * K + k0 + j * 4);
                int brow = i >> 5, bcol = (i & 31) * 4;
                cp16(&Bs[st][brow * BS_STRIDE + bcol],
                     Wb + (size_t)(k0 + brow) * Ncols + bcol);
            }
        };
        issue(0); CP_COMMIT();
        issue(1); CP_COMMIT();
        const int NCH = K / 32;
#pragma unroll 1
        for (int ch = 0; ch < NCH; ch++) {
            CP_WAIT1();
            __syncthreads();
            if (ch + 2 < NCH) issue(ch + 2);
            CP_COMMIT();
            int st = ch % 3;
            const uint32_t* As32 = (const uint32_t*)As[st];
            const uint32_t* Bs32 = (const uint32_t*)Bs[st];
#pragma unroll
            for (int ks = 0; ks < 4; ks++) {
                int kk = ks * 8;
                uint32_t a[4][4], b[4][2];
#pragma unroll
                for (int mt = 0; mt < 4; mt++) {
                    int r = wm + mt * 16 + g;
                    a[mt][0] = As32[r * AS_STRIDE + kk + lk];
                    a[mt][1] = As32[(r + 8) * AS_STRIDE + kk + lk];
                    a[mt][2] = As32[r * AS_STRIDE + kk + lk + 4];
                    a[mt][3] = As32[(r + 8) * AS_STRIDE + kk + lk + 4];
                }
#pragma unroll
                for (int nt = 0; nt < 4; nt++) {
                    int c = wn + nt * 8 + g;
                    b[nt][0] = Bs32[(kk + lk) * BS_STRIDE + c];
                    b[nt][1] = Bs32[(kk + lk + 4) * BS_STRIDE + c];
                }
#pragma unroll
                for (int mt = 0; mt < 4; mt++)
#pragma unroll
                    for (int nt = 0; nt < 4; nt++)
                        mma_1688(acc[mt][nt], a[mt], b[nt]);
            }
        }
    }
};

// ---------------------------------------------------------------------------
// Fused Q + KV projection GEMM. grid (24, 32): bx<8 -> Q, else KV.
// Epilogue rounds to tf32 (Q additionally pre-scaled by SCALE_).
// ---------------------------------------------------------------------------
__global__ __launch_bounds__(256, 2) void mma_gemm_qkv(
    const float* __restrict__ bq, const float* __restrict__ bkv)
{
    extern __shared__ float smem[];
    bool isQ = blockIdx.x < 8;
    const float* A = isQ ? g_x32 : g_c32;
    const float* W = isQ ? g_wq32 : g_wkv32;
    const float* bias = isQ ? bq : bkv;
    int Ncols = isQ ? DIM_ : 2 * DIM_;
    int bN = (isQ ? blockIdx.x : blockIdx.x - 8) * 128;
    int bM = blockIdx.y * 128;

    int tid = threadIdx.x;
    int wid = tid >> 5, lane = tid & 31;
    int g = lane >> 2, lk = lane & 3;
    int wm = (wid & 1) * 64, wn = (wid >> 1) * 32;

    GemmCore core;
    core.run(smem, A + (size_t)bM * DIM_, W + bN, Ncols, DIM_, tid, g, lk, wm, wn);

#pragma unroll
    for (int mt = 0; mt < 4; mt++) {
#pragma unroll
        for (int nt = 0; nt < 4; nt++) {
            int gCol = bN + wn + nt * 8 + 2 * lk;
            float bx = bias[gCol], by = bias[gCol + 1];
#pragma unroll
            for (int half = 0; half < 2; half++) {
                int gRow = bM + wm + mt * 16 + g + half * 8;
                float vx = core.acc[mt][nt][half * 2 + 0] + bx;
                float vy = core.acc[mt][nt][half * 2 + 1] + by;
                int bb = gRow >> 10, r = gRow & 1023;
                if (isQ) {
                    int h = gCol >> 6, d = gCol & 63;
                    float2 o = make_float2(to_tf32(vx * SCALE_), to_tf32(vy * SCALE_));
                    *(float2*)(g_q + (((size_t)(bb * H_ + h)) * N_ + r) * D_ + d) = o;
                } else {
                    int cc = gCol & 1023;
                    int h = cc >> 6, d = cc & 63;
                    float* dst = (gCol < DIM_) ? g_k : g_v;
                    float2 o = make_float2(to_tf32(vx), to_tf32(vy));
                    *(float2*)(dst + (((size_t)(bb * H_ + h)) * M_ + r) * D_ + d) = o;
                }
            }
        }
    }
}

// ---------------------------------------------------------------------------
// Output projection GEMM: out = g_ao @ g_wp32 + bp (no rounding; final fp32)
// ---------------------------------------------------------------------------
__global__ __launch_bounds__(256, 2) void mma_gemm_out(
    const float* __restrict__ bias, float* __restrict__ C)
{
    extern __shared__ float smem[];
    int bN = blockIdx.x * 128, bM = blockIdx.y * 128;
    int tid = threadIdx.x;
    int wid = tid >> 5, lane = tid & 31;
    int g = lane >> 2, lk = lane & 3;
    int wm = (wid & 1) * 64, wn = (wid >> 1) * 32;

    GemmCore core;
    core.run(smem, g_ao + (size_t)bM * DIM_, g_wp32 + bN, DIM_, DIM_,
             tid, g, lk, wm, wn);

#pragma unroll
    for (int mt = 0; mt < 4; mt++) {
#pragma unroll
        for (int nt = 0; nt < 4; nt++) {
            int gCol = bN + wn + nt * 8 + 2 * lk;
            float bx = bias[gCol], by = bias[gCol + 1];
#pragma unroll
            for (int half = 0; half < 2; half++) {
                int gRow = bM + wm + mt * 16 + g + half * 8;
                float vx = core.acc[mt][nt][half * 2 + 0] + bx;
                float vy = core.acc[mt][nt][half * 2 + 1] + by;
                *(float2*)(C + (size_t)gRow * DIM_ + gCol) = make_float2(vx, vy);
            }
        }
    }
}

// ---------------------------------------------------------------------------
// Flash attention v2: k-tile 64, cp.async loads, 110.6KB smem -> 2 CTAs/SM.
// 256 thr = 8 warps: rows 2 groups x 64, cols 4 groups x 16.
// Inputs g_q/g_k/g_v already tf32-rounded (Q pre-scaled).
// ---------------------------------------------------------------------------
constexpr int QS_S = 68, KS_S = 68, VS_S = 72, PS_S = 68;
constexpr int KT = 64;
constexpr int SMEM_ATTN =
    (128 * QS_S + KT * KS_S + KT * VS_S + 128 * PS_S + 512 + 512 + 256) * 4; // 110592

__global__ __launch_bounds__(256, 2) void attn_mma_kernel() {
    extern __shared__ float sm[];
    float* Qs = sm;                        // [128][68]
    float* Ks = Qs + 128 * QS_S;           // [64][68]
    float* Vs = Ks + KT * KS_S;            // [64][72]
    float* Ps = Vs + KT * VS_S;            // [128][68]
    float* redmax = Ps + 128 * PS_S;       // [4][128]
    float* redsum = redmax + 512;          // [4][128]
    unsigned* Ms = (unsigned*)(redsum + 512); // [128][2]

    const uint32_t* Qs32 = (const uint32_t*)Qs;
    const uint32_t* Ks32 = (const uint32_t*)Ks;
    const uint32_t* Vs32 = (const uint32_t*)Vs;
    const uint32_t* Ps32 = (const uint32_t*)Ps;

    int tid = threadIdx.x;
    int wid = tid >> 5, lane = tid & 31;
    int g = lane >> 2, lk = lane & 3;
    int wm = (wid & 1) * 64;
    int cg = wid >> 1;            // 0..3 column group
    int wn = cg * 16;             // S cols (16 wide)
    int on = cg * 16;             // O cols (16 wide)
    int n0 = blockIdx.x * 128;
    int h = blockIdx.y, b = blockIdx.z;

    const float* qp = g_q + (((size_t)(b * H_ + h)) * N_ + n0) * D_;
    const float* kp = g_k + ((size_t)(b * H_ + h)) * M_ * D_;
    const float* vp = g_v + ((size_t)(b * H_ + h)) * M_ * D_;
    const unsigned* mbp = g_mbits + ((size_t)(b * N_) + n0) * (M_ / 32);

    // Q tile (pure copy; already tf32*SCALE)
#pragma unroll
    for (int it = 0; it < 8; it++) {
        int i = tid + it * 256;
        int row = i >> 4, c = (i & 15) * 4;
        cp16(&Qs[row * QS_S + c], qp + (size_t)row * D_ + c);
    }

    float acc_o[4][2][4];
#pragma unroll
    for (int mt = 0; mt < 4; mt++)
#pragma unroll
        for (int nt = 0; nt < 2; nt++)
#pragma unroll
            for (int i = 0; i < 4; i++) acc_o[mt][nt][i] = 0.f;
    float row_max[8], row_l[8];
#pragma unroll
    for (int i = 0; i < 8; i++) { row_max[i] = -1e30f; row_l[i] = 0.f; }

#pragma unroll 1
    for (int m0 = 0; m0 < M_; m0 += KT) {
        __syncthreads();   // prev tile consumed
        // K/V tiles + mask via cp.async
#pragma unroll
        for (int it = 0; it < 4; it++) {
            int i = tid + it * 256;
            int row = i >> 4, c = (i & 15) * 4;
            cp16(&Ks[row * KS_S + c], kp + (size_t)(m0 + row) * D_ + c);
            cp16(&Vs[row * VS_S + c], vp + (size_t)(m0 + row) * D_ + c);
        }
        if (tid < 128)
            cp8(&Ms[tid * 2], mbp + (size_t)tid * (M_ / 32) + (m0 >> 5));
        CP_COMMIT();
        CP_WAIT0();
        __syncthreads();

        // ---- S = Q @ K^T  (S tile 128x64; warp tile 64x16) ----
        float acc_s[4][2][4];
#pragma unroll
        for (int mt = 0; mt < 4; mt++)
#pragma unroll
            for (int nt = 0; nt < 2; nt++)
#pragma unroll
                for (int i = 0; i < 4; i++) acc_s[mt][nt][i] = 0.f;
#pragma unroll
        for (int ks = 0; ks < 8; ks++) {
            int kk = ks * 8;
            uint32_t a[4][4], bf[2][2];
#pragma unroll
            for (int mt = 0; mt < 4; mt++) {
                int r = wm + mt * 16 + g;
                a[mt][0] = Qs32[r * QS_S + kk + lk];
                a[mt][1] = Qs32[(r + 8) * QS_S + kk + lk];
                a[mt][2] = Qs32[r * QS_S + kk + lk + 4];
                a[mt][3] = Qs32[(r + 8) * QS_S + kk + lk + 4];
            }
#pragma unroll
            for (int nt = 0; nt < 2; nt++) {
                int c = wn + nt * 8 + g;
                bf[nt][0] = Ks32[c * KS_S + kk + lk];
                bf[nt][1] = Ks32[c * KS_S + kk + lk + 4];
            }
#pragma unroll
            for (int mt = 0; mt < 4; mt++)
#pragma unroll
                for (int nt = 0; nt < 2; nt++)
                    mma_1688(acc_s[mt][nt], a[mt], bf[nt]);
        }

        // ---- mask + per-warp row max ----
        int mword = cg >> 1;
        int bit0 = (cg & 1) * 16;
#pragma unroll
        for (int mt = 0; mt < 4; mt++) {
#pragma unroll
            for (int half = 0; half < 2; half++) {
                int rloc = wm + mt * 16 + g + half * 8;
                unsigned mw = Ms[rloc * 2 + mword];
                float mx = -1e30f;
#pragma unroll
                for (int nt = 0; nt < 2; nt++) {
                    int bit = bit0 + nt * 8 + 2 * lk;
                    float s0 = acc_s[mt][nt][half * 2 + 0];
                    float s1 = acc_s[mt][nt][half * 2 + 1];
                    if (!((mw >> bit) & 1u)) s0 = -INFINITY;
                    if (!((mw >> (bit + 1)) & 1u)) s1 = -INFINITY;
                    acc_s[mt][nt][half * 2 + 0] = s0;
                    acc_s[mt][nt][half * 2 + 1] = s1;
                    mx = fmaxf(mx, fmaxf(s0, s1));
                }
                mx = fmaxf(mx, __shfl_xor_sync(0xffffffffu, mx, 1));
                mx = fmaxf(mx, __shfl_xor_sync(0xffffffffu, mx, 2));
                if (lk == 0) redmax[cg * 128 + rloc] = mx;
            }
        }
        __syncthreads();

        // ---- finalize max, P (tf32), partial sums, rescale O ----
        float corr_s[8];
#pragma unroll
        for (int mt = 0; mt < 4; mt++) {
#pragma unroll
            for (int half = 0; half < 2; half++) {
                int ri = mt * 2 + half;
                int rloc = wm + mt * 16 + g + half * 8;
                float mx = fmaxf(fmaxf(redmax[rloc], redmax[128 + rloc]),
                                 fmaxf(redmax[256 + rloc], redmax[384 + rloc]));
                float nm = fmaxf(fmaxf(row_max[ri], mx), -1e30f);
                float corr = __expf(row_max[ri] - nm);
                row_max[ri] = nm;
                corr_s[ri] = corr;
                float lsum = 0.f;
#pragma unroll
                for (int nt = 0; nt < 2; nt++) {
                    float p0 = to_tf32(__expf(acc_s[mt][nt][half * 2 + 0] - nm));
                    float p1 = to_tf32(__expf(acc_s[mt][nt][half * 2 + 1] - nm));
                    lsum += p0 + p1;
                    *(float2*)&Ps[rloc * PS_S + wn + nt * 8 + 2 * lk] =
                        make_float2(p0, p1);
                }
                lsum += __shfl_xor_sync(0xffffffffu, lsum, 1);
                lsum += __shfl_xor_sync(0xffffffffu, lsum, 2);
                if (lk == 0) redsum[cg * 128 + rloc] = lsum;
#pragma unroll
                for (int nt = 0; nt < 2; nt++) {
                    acc_o[mt][nt][half * 2 + 0] *= corr;
                    acc_o[mt][nt][half * 2 + 1] *= corr;
                }
            }
        }
        __syncthreads();

#pragma unroll
        for (int mt = 0; mt < 4; mt++) {
#pragma unroll
            for (int half = 0; half < 2; half++) {
                int ri = mt * 2 + half;
                int rloc = wm + mt * 16 + g + half * 8;
                float ts = (redsum[rloc] + redsum[128 + rloc]) +
                           (redsum[256 + rloc] + redsum[384 + rloc]);
                row_l[ri] = row_l[ri] * corr_s[ri] + ts;
            }
        }

        // ---- O += P @ V ----
#pragma unroll
        for (int ks = 0; ks < 8; ks++) {
            int kk = ks * 8;
            uint32_t a[4][4], bf[2][2];
#pragma unroll
            for (int mt = 0; mt < 4; mt++) {
                int r = wm + mt * 16 + g;
                a[mt][0] = Ps32[r * PS_S + kk + lk];
                a[mt][1] = Ps32[(r + 8) * PS_S + kk + lk];
                a[mt][2] = Ps32[r * PS_S + kk + lk + 4];
                a[mt][3] = Ps32[(r + 8) * PS_S + kk + lk + 4];
            }
#pragma unroll
            for (int nt = 0; nt < 2; nt++) {
                int c = on + nt * 8 + g;
                bf[nt][0] = Vs32[(kk + lk) * VS_S + c];
                bf[nt][1] = Vs32[(kk + lk + 4) * VS_S + c];
            }
#pragma unroll
            for (int mt = 0; mt < 4; mt++)
#pragma unroll
                for (int nt = 0; nt < 2; nt++)
                    mma_1688(acc_o[mt][nt], a[mt], bf[nt]);
        }
    }

    // Epilogue: normalize + tf32-round for the out-projection cp.async path
#pragma unroll
    for (int mt = 0; mt < 4; mt++) {
#pragma unroll
        for (int half = 0; half < 2; half++) {
            int ri = mt * 2 + half;
            int rloc = wm + mt * 16 + g + half * 8;
            float inv = 1.0f / row_l[ri];
#pragma unroll
            for (int nt = 0; nt < 2; nt++) {
                int c = on + nt * 8 + 2 * lk;
                float2 o = make_float2(to_tf32(acc_o[mt][nt][half * 2 + 0] * inv),
                                       to_tf32(acc_o[mt][nt][half * 2 + 1] * inv));
                *(float2*)(g_ao + ((size_t)(b * N_) + n0 + rloc) * DIM_ +
                           h * D_ + c) = o;
            }
        }
    }
}

// ---------------------------------------------------------------------------
// Launch
// ---------------------------------------------------------------------------
extern "C" void kernel_launch(void* const* d_in, const int* in_sizes, int n_in,
                              void* d_out, int out_size) {
    const float* x   = (const float*)d_in[0];
    const float* ctx = (const float*)d_in[1];
    const int*   msk = (const int*)d_in[2];
    const float* Wq  = (const float*)d_in[3];
    const float* bq  = (const float*)d_in[4];
    const float* Wkv = (const float*)d_in[5];
    const float* bkv = (const float*)d_in[6];
    const float* Wp  = (const float*)d_in[7];
    const float* bp  = (const float*)d_in[8];
    float* out = (float*)d_out;

    cudaFuncSetAttribute(attn_mma_kernel,
                         cudaFuncAttributeMaxDynamicSharedMemorySize, SMEM_ATTN);
    cudaFuncSetAttribute(mma_gemm_qkv,
                         cudaFuncAttributeMaxDynamicSharedMemorySize, SMEM_GEMM);
    cudaFuncSetAttribute(mma_gemm_out,
                         cudaFuncAttributeMaxDynamicSharedMemorySize, SMEM_GEMM);

    pack_mask_kernel<<<(B_ * N_) / 8, 256>>>(msk);
    tf32_round_all<<<3145728 / 256, 256>>>(x, ctx, Wq, Wkv, Wp);
    mma_gemm_qkv<<<dim3(24, 32), 256, SMEM_GEMM>>>(bq, bkv);
    attn_mma_kernel<<<dim3(N_ / 128, H_, B_), 256, SMEM_ATTN>>>();
    mma_gemm_out<<<dim3(8, 32), 256, SMEM_GEMM>>>(bp, out);
}

// round 17
// speedup vs baseline: 3.9248x; 1.0267x over previous
#include <cuda_runtime.h>
#include <cstdint>

// Problem constants
constexpr int B_ = 4, H_ = 16, N_ = 1024, M_ = 1024, D_ = 64, DIM_ = 1024;
constexpr float SCALE_ = 0.125f;   // 64^-0.5

// Scratch (device globals — no allocation allowed)
__device__ float g_q[(size_t)B_ * H_ * N_ * D_];        // [b,h,n,d] tf32(q*SCALE)
__device__ float g_k[(size_t)B_ * H_ * M_ * D_];        // [b,h,m,d] tf32
__device__ float g_v[(size_t)B_ * H_ * M_ * D_];        // [b,h,m,d] tf32
__device__ float g_ao[(size_t)B_ * N_ * DIM_];          // [b,n,h*d] tf32
__device__ unsigned g_mbits[(size_t)B_ * N_ * (M_ / 32)]; // packed mask bits
// tf32 pre-rounded copies of inputs/weights
__device__ float g_x32[(size_t)B_ * N_ * DIM_];
__device__ float g_c32[(size_t)B_ * M_ * DIM_];
__device__ float g_wq32[(size_t)DIM_ * DIM_];
__device__ float g_wkv32[(size_t)DIM_ * 2 * DIM_];
__device__ float g_wp32[(size_t)DIM_ * DIM_];

// ---------------------------------------------------------------------------
// Helpers
// ---------------------------------------------------------------------------
__device__ __forceinline__ float to_tf32(float x) {
    float r; asm("cvt.rna.tf32.f32 %0, %1;" : "=f"(r) : "f"(x)); return r;
}
__device__ __forceinline__ void mma_1688(float* d, const uint32_t* a, const uint32_t* b) {
    asm volatile(
        "mma.sync.aligned.m16n8k8.row.col.f32.tf32.tf32.f32 "
        "{%0,%1,%2,%3}, {%4,%5,%6,%7}, {%8,%9}, {%0,%1,%2,%3};"
        : "+f"(d[0]), "+f"(d[1]), "+f"(d[2]), "+f"(d[3])
        : "r"(a[0]), "r"(a[1]), "r"(a[2]), "r"(a[3]), "r"(b[0]), "r"(b[1]));
}
__device__ __forceinline__ void cp16(void* smem_dst, const void* gsrc) {
    uint32_t s = (uint32_t)__cvta_generic_to_shared(smem_dst);
    asm volatile("cp.async.cg.shared.global [%0], [%1], 16;" :: "r"(s), "l"(gsrc));
}
#define CP_COMMIT() asm volatile("cp.async.commit_group;" ::: "memory")
#define CP_WAIT1()  asm volatile("cp.async.wait_group 1;" ::: "memory")

// ---------------------------------------------------------------------------
// Fused tf32 pre-round of all 5 tensors (segment lookup on flat float4 index)
// ---------------------------------------------------------------------------
__global__ __launch_bounds__(256) void tf32_round_all(
    const float* __restrict__ x, const float* __restrict__ ctx,
    const float* __restrict__ Wq, const float* __restrict__ Wkv,
    const float* __restrict__ Wp)
{
    size_t i = (size_t)blockIdx.x * 256 + threadIdx.x;   // float4 index
    const float* src; float* dst; size_t off;
    if (i < 1048576)      { src = x;   dst = g_x32;  off = i; }
    else if (i < 2097152) { src = ctx; dst = g_c32;  off = i - 1048576; }
    else if (i < 2359296) { src = Wq;  dst = g_wq32; off = i - 2097152; }
    else if (i < 2883584) { src = Wkv; dst = g_wkv32; off = i - 2359296; }
    else                  { src = Wp;  dst = g_wp32; off = i - 2883584; }
    float4 v = *(const float4*)(src + off * 4);
    v.x = to_tf32(v.x); v.y = to_tf32(v.y);
    v.z = to_tf32(v.z); v.w = to_tf32(v.w);
    *(float4*)(dst + off * 4) = v;
}

// ---------------------------------------------------------------------------
// Pack int32 mask [b,n,1024] into bitmask words [b,n,32]
// ---------------------------------------------------------------------------
__global__ __launch_bounds__(256) void pack_mask_kernel(const int* __restrict__ mask) {
    int lane = threadIdx.x & 31;
    int row = blockIdx.x * 8 + (threadIdx.x >> 5);
    const int* mrow = mask + (size_t)row * M_;
    unsigned* brow = g_mbits + (size_t)row * (M_ / 32);
#pragma unroll 4
    for (int w = 0; w < M_ / 32; w++) {
        int v = mrow[w * 32 + lane];
        unsigned bits = __ballot_sync(0xffffffffu, v != 0);
        if (lane == 0) brow[w] = bits;
    }
}

// ---------------------------------------------------------------------------
// GEMM core (shared by both GEMM kernels): 128x128 tile, cp.async 3-stage
// ---------------------------------------------------------------------------
constexpr int AS_STRIDE = 36;
constexpr int BS_STRIDE = 136;
constexpr int A_STAGE = 128 * AS_STRIDE;
constexpr int B_STAGE = 32 * BS_STRIDE;
constexpr int SMEM_GEMM = 3 * (A_STAGE + B_STAGE) * 4;  // 107520 B

struct GemmCore {
    float acc[4][4][4];
    __device__ __forceinline__ void run(
        float* smem, const float* Ab, const float* Wb, int Ncols, int K,
        int tid, int g, int lk, int wm, int wn)
    {
        float* As[3] = { smem, smem + A_STAGE, smem + 2 * A_STAGE };
        float* Bs[3] = { smem + 3 * A_STAGE, smem + 3 * A_STAGE + B_STAGE,
                         smem + 3 * A_STAGE + 2 * B_STAGE };
#pragma unroll
        for (int mt = 0; mt < 4; mt++)
#pragma unroll
            for (int nt = 0; nt < 4; nt++)
#pragma unroll
                for (int i = 0; i < 4; i++) acc[mt][nt][i] = 0.f;

        auto issue = [&](int ch) {
            int k0 = ch * 32, st = ch % 3;
#pragma unroll
            for (int it = 0; it < 4; it++) {
                int i = tid + it * 256;
                int row = i >> 3, j = i & 7;
                cp16(&As[st][row * AS_STRIDE + j * 4],
                     Ab + (size_t)row * K + k0 + j * 4);
                int brow = i >> 5, bcol = (i & 31) * 4;
                cp16(&Bs[st][brow * BS_STRIDE + bcol],
                     Wb + (size_t)(k0 + brow) * Ncols + bcol);
            }
        };
        issue(0); CP_COMMIT();
        issue(1); CP_COMMIT();
        const int NCH = K / 32;
#pragma unroll 1
        for (int ch = 0; ch < NCH; ch++) {
            CP_WAIT1();
            __syncthreads();
            if (ch + 2 < NCH) issue(ch + 2);
            CP_COMMIT();
            int st = ch % 3;
            const uint32_t* As32 = (const uint32_t*)As[st];
            const uint32_t* Bs32 = (const uint32_t*)Bs[st];
#pragma unroll
            for (int ks = 0; ks < 4; ks++) {
                int kk = ks * 8;
                uint32_t a[4][4], b[4][2];
#pragma unroll
                for (int mt = 0; mt < 4; mt++) {
                    int r = wm + mt * 16 + g;
                    a[mt][0] = As32[r * AS_STRIDE + kk + lk];
                    a[mt][1] = As32[(r + 8) * AS_STRIDE + kk + lk];
                    a[mt][2] = As32[r * AS_STRIDE + kk + lk + 4];
                    a[mt][3] = As32[(r + 8) * AS_STRIDE + kk + lk + 4];
                }
#pragma unroll
                for (int nt = 0; nt < 4; nt++) {
                    int c = wn + nt * 8 + g;
                    b[nt][0] = Bs32[(kk + lk) * BS_STRIDE + c];
                    b[nt][1] = Bs32[(kk + lk + 4) * BS_STRIDE + c];
                }
#pragma unroll
                for (int mt = 0; mt < 4; mt++)
#pragma unroll
                    for (int nt = 0; nt < 4; nt++)
                        mma_1688(acc[mt][nt], a[mt], b[nt]);
            }
        }
    }
};

// ---------------------------------------------------------------------------
// Fused Q + KV projection GEMM. grid (24, 32): bx<8 -> Q, else KV.
// Epilogue rounds to tf32 (Q additionally pre-scaled by SCALE_).
// ---------------------------------------------------------------------------
__global__ __launch_bounds__(256, 2) void mma_gemm_qkv(
    const float* __restrict__ bq, const float* __restrict__ bkv)
{
    extern __shared__ float smem[];
    bool isQ = blockIdx.x < 8;
    const float* A = isQ ? g_x32 : g_c32;
    const float* W = isQ ? g_wq32 : g_wkv32;
    const float* bias = isQ ? bq : bkv;
    int Ncols = isQ ? DIM_ : 2 * DIM_;
    int bN = (isQ ? blockIdx.x : blockIdx.x - 8) * 128;
    int bM = blockIdx.y * 128;

    int tid = threadIdx.x;
    int wid = tid >> 5, lane = tid & 31;
    int g = lane >> 2, lk = lane & 3;
    int wm = (wid & 1) * 64, wn = (wid >> 1) * 32;

    GemmCore core;
    core.run(smem, A + (size_t)bM * DIM_, W + bN, Ncols, DIM_, tid, g, lk, wm, wn);

#pragma unroll
    for (int mt = 0; mt < 4; mt++) {
#pragma unroll
        for (int nt = 0; nt < 4; nt++) {
            int gCol = bN + wn + nt * 8 + 2 * lk;
            float bx = bias[gCol], by = bias[gCol + 1];
#pragma unroll
            for (int half = 0; half < 2; half++) {
                int gRow = bM + wm + mt * 16 + g + half * 8;
                float vx = core.acc[mt][nt][half * 2 + 0] + bx;
                float vy = core.acc[mt][nt][half * 2 + 1] + by;
                int bb = gRow >> 10, r = gRow & 1023;
                if (isQ) {
                    int h = gCol >> 6, d = gCol & 63;
                    float2 o = make_float2(to_tf32(vx * SCALE_), to_tf32(vy * SCALE_));
                    *(float2*)(g_q + (((size_t)(bb * H_ + h)) * N_ + r) * D_ + d) = o;
                } else {
                    int cc = gCol & 1023;
                    int h = cc >> 6, d = cc & 63;
                    float* dst = (gCol < DIM_) ? g_k : g_v;
                    float2 o = make_float2(to_tf32(vx), to_tf32(vy));
                    *(float2*)(dst + (((size_t)(bb * H_ + h)) * M_ + r) * D_ + d) = o;
                }
            }
        }
    }
}

// ---------------------------------------------------------------------------
// Output projection GEMM: out = g_ao @ g_wp32 + bp (no rounding; final fp32)
// ---------------------------------------------------------------------------
__global__ __launch_bounds__(256, 2) void mma_gemm_out(
    const float* __restrict__ bias, float* __restrict__ C)
{
    extern __shared__ float smem[];
    int bN = blockIdx.x * 128, bM = blockIdx.y * 128;
    int tid = threadIdx.x;
    int wid = tid >> 5, lane = tid & 31;
    int g = lane >> 2, lk = lane & 3;
    int wm = (wid & 1) * 64, wn = (wid >> 1) * 32;

    GemmCore core;
    core.run(smem, g_ao + (size_t)bM * DIM_, g_wp32 + bN, DIM_, DIM_,
             tid, g, lk, wm, wn);

#pragma unroll
    for (int mt = 0; mt < 4; mt++) {
#pragma unroll
        for (int nt = 0; nt < 4; nt++) {
            int gCol = bN + wn + nt * 8 + 2 * lk;
            float bx = bias[gCol], by = bias[gCol + 1];
#pragma unroll
            for (int half = 0; half < 2; half++) {
                int gRow = bM + wm + mt * 16 + g + half * 8;
                float vx = core.acc[mt][nt][half * 2 + 0] + bx;
                float vy = core.acc[mt][nt][half * 2 + 1] + by;
                *(float2*)(C + (size_t)gRow * DIM_ + gCol) = make_float2(vx, vy);
            }
        }
    }
}

// ---------------------------------------------------------------------------
// Flash attention v3 (FA2-style, fixed tile strides): warp owns 16 rows;
// KT=32 key tiles, 3-stage cp.async pipeline, 1 syncthreads/tile; softmax
// in-warp (quad shfl); P via in-warp shfl transpose (no smem round-trip).
// K rows stride 68 words (68%32=4: frag addr g*4+lk -> 32 banks),
// V rows stride 72 words (72%32=8: frag addr 8*lk+g -> 32 banks).
// ---------------------------------------------------------------------------
constexpr int KT_A = 32;
constexpr int NT_A = M_ / KT_A;               // 32 tiles
constexpr int KQF = 8192;                     // Q fragment-major words
constexpr int KS_AT = 68;                     // K stage row stride (words)
constexpr int VS_AT = 72;                     // V stage row stride (words)
constexpr int KST = KT_A * KS_AT;             // 2176 words / stage
constexpr int VST = KT_A * VS_AT;             // 2304 words / stage
constexpr int SMEM_ATTN = (KQF + 3 * KST + 3 * VST) * 4;   // 86528 B

__global__ __launch_bounds__(256, 2) void attn_mma_kernel() {
    extern __shared__ float sm[];
    float* QF = sm;
    float* Kst[3] = { sm + KQF, sm + KQF + KST, sm + KQF + 2 * KST };
    float* Vst[3] = { sm + KQF + 3 * KST, sm + KQF + 3 * KST + VST,
                      sm + KQF + 3 * KST + 2 * VST };

    int tid = threadIdx.x;
    int wid = tid >> 5, lane = tid & 31;
    int g = lane >> 2, lk = lane & 3;
    int wm = wid * 16;                // this warp's 16 rows
    int n0 = blockIdx.x * 128;
    int h = blockIdx.y, b = blockIdx.z;

    const float* qp = g_q + (((size_t)(b * H_ + h)) * N_ + n0) * D_;
    const float* kp = g_k + ((size_t)(b * H_ + h)) * M_ * D_;
    const float* vp = g_v + ((size_t)(b * H_ + h)) * M_ * D_;
    const unsigned* mbp = g_mbits + ((size_t)(b * N_) + n0) * (M_ / 32);

    // ---- Q -> fragment-major smem (one-time) ----
    // word layout: QF[w*1024 + ks*128 + g*16 + lk*4 + (hi + 2*hh)]
#pragma unroll
    for (int i = 0; i < 8; i++) {
        int idx = tid + i * 256;
        int row = idx >> 4, j = idx & 15;
        float4 qv = *(const float4*)(qp + (size_t)row * D_ + j * 4);
        int w = row >> 4, rr = row & 15, g2 = rr & 7, hi = rr >> 3;
        int ks = j >> 1, hh = j & 1;
        float* base = QF + w * 1024 + ks * 128 + g2 * 16 + hi + 2 * hh;
        base[0] = qv.x; base[4] = qv.y; base[8] = qv.z; base[12] = qv.w;
    }

    // K/V tile loader: 32 rows x 64 floats = 512 float4 each; 2 per thread
    auto issue = [&](int t) {
        int st = t % 3;
#pragma unroll
        for (int it = 0; it < 2; it++) {
            int i = tid + it * 256;
            int row = i >> 4, j = i & 15;
            cp16(Kst[st] + row * KS_AT + j * 4,
                 kp + (size_t)(t * KT_A + row) * D_ + j * 4);
            cp16(Vst[st] + row * VS_AT + j * 4,
                 vp + (size_t)(t * KT_A + row) * D_ + j * 4);
        }
    };

    float acc_o[8][4];
#pragma unroll
    for (int v = 0; v < 8; v++)
#pragma unroll
        for (int i = 0; i < 4; i++) acc_o[v][i] = 0.f;
    float row_max0 = -1e30f, row_max1 = -1e30f, row_l0 = 0.f, row_l1 = 0.f;

    issue(0); CP_COMMIT();
    issue(1); CP_COMMIT();

    int srcA = g * 4 + (lk >> 1), srcB = srcA + 2;
    bool selo = (lk & 1);

#pragma unroll 1
    for (int t = 0; t < NT_A; t++) {
        CP_WAIT1();
        __syncthreads();      // buf t ready; compute(t-1) done -> stage reuse safe
        if (t + 2 < NT_A) issue(t + 2);
        CP_COMMIT();          // unconditional: keeps group counting exact

        unsigned mwA = mbp[(size_t)(wm + g) * (M_ / 32) + t];
        unsigned mwB = mbp[(size_t)(wm + g + 8) * (M_ / 32) + t];

        int st = t % 3;
        const uint32_t* Kp = (const uint32_t*)Kst[st];
        const uint32_t* Vp = (const uint32_t*)Vst[st];

        // ---- S = Q @ K^T  (warp tile 16 x 32) ----
        float s[4][4];
#pragma unroll
        for (int nt = 0; nt < 4; nt++)
#pragma unroll
            for (int i = 0; i < 4; i++) s[nt][i] = 0.f;
#pragma unroll
        for (int ks = 0; ks < 8; ks++) {
            uint4 aq = *(const uint4*)(QF + wid * 1024 + ks * 128 + g * 16 + lk * 4);
            uint32_t a[4] = { aq.x, aq.y, aq.z, aq.w };
#pragma unroll
            for (int nt = 0; nt < 4; nt++) {
                int c = nt * 8 + g;
                uint32_t bf[2];
                bf[0] = Kp[c * KS_AT + ks * 8 + lk];
                bf[1] = Kp[c * KS_AT + ks * 8 + lk + 4];
                mma_1688(s[nt], a, bf);
            }
        }

        // ---- mask + in-warp online softmax ----
        float mxA = -1e30f, mxB = -1e30f;
#pragma unroll
        for (int nt = 0; nt < 4; nt++) {
            int bit = nt * 8 + 2 * lk;
            if (!((mwA >> bit) & 1u))       s[nt][0] = -INFINITY;
            if (!((mwA >> (bit + 1)) & 1u)) s[nt][1] = -INFINITY;
            if (!((mwB >> bit) & 1u))       s[nt][2] = -INFINITY;
            if (!((mwB >> (bit + 1)) & 1u)) s[nt][3] = -INFINITY;
            mxA = fmaxf(mxA, fmaxf(s[nt][0], s[nt][1]));
            mxB = fmaxf(mxB, fmaxf(s[nt][2], s[nt][3]));
        }
        mxA = fmaxf(mxA, __shfl_xor_sync(0xffffffffu, mxA, 1));
        mxA = fmaxf(mxA, __shfl_xor_sync(0xffffffffu, mxA, 2));
        mxB = fmaxf(mxB, __shfl_xor_sync(0xffffffffu, mxB, 1));
        mxB = fmaxf(mxB, __shfl_xor_sync(0xffffffffu, mxB, 2));

        float nmA = fmaxf(fmaxf(row_max0, mxA), -1e30f);
        float nmB = fmaxf(fmaxf(row_max1, mxB), -1e30f);
        float corrA = __expf(row_max0 - nmA);
        float corrB = __expf(row_max1 - nmB);
        row_max0 = nmA; row_max1 = nmB;

        float lsA = 0.f, lsB = 0.f;
#pragma unroll
        for (int nt = 0; nt < 4; nt++) {
            float p0 = to_tf32(__expf(s[nt][0] - nmA));
            float p1 = to_tf32(__expf(s[nt][1] - nmA));
            float p2 = to_tf32(__expf(s[nt][2] - nmB));
            float p3 = to_tf32(__expf(s[nt][3] - nmB));
            s[nt][0] = p0; s[nt][1] = p1; s[nt][2] = p2; s[nt][3] = p3;
            lsA += p0 + p1; lsB += p2 + p3;
        }
        lsA += __shfl_xor_sync(0xffffffffu, lsA, 1);
        lsA += __shfl_xor_sync(0xffffffffu, lsA, 2);
        lsB += __shfl_xor_sync(0xffffffffu, lsB, 1);
        lsB += __shfl_xor_sync(0xffffffffu, lsB, 2);
        row_l0 = row_l0 * corrA + lsA;
        row_l1 = row_l1 * corrB + lsB;

#pragma unroll
        for (int v = 0; v < 8; v++) {
            acc_o[v][0] *= corrA; acc_o[v][1] *= corrA;
            acc_o[v][2] *= corrB; acc_o[v][3] *= corrB;
        }

        // ---- O += P @ V  (P fragments via in-warp shfl transpose) ----
#pragma unroll
        for (int ks = 0; ks < 4; ks++) {
            float v00 = __shfl_sync(0xffffffffu, s[ks][0], srcA);
            float v01 = __shfl_sync(0xffffffffu, s[ks][1], srcA);
            float v10 = __shfl_sync(0xffffffffu, s[ks][2], srcA);
            float v11 = __shfl_sync(0xffffffffu, s[ks][3], srcA);
            float v20 = __shfl_sync(0xffffffffu, s[ks][0], srcB);
            float v21 = __shfl_sync(0xffffffffu, s[ks][1], srcB);
            float v30 = __shfl_sync(0xffffffffu, s[ks][2], srcB);
            float v31 = __shfl_sync(0xffffffffu, s[ks][3], srcB);
            uint32_t a[4];
            a[0] = __float_as_uint(selo ? v01 : v00);
            a[1] = __float_as_uint(selo ? v11 : v10);
            a[2] = __float_as_uint(selo ? v21 : v20);
            a[3] = __float_as_uint(selo ? v31 : v30);
#pragma unroll
            for (int nv = 0; nv < 8; nv++) {
                uint32_t bf[2];
                bf[0] = Vp[(ks * 8 + lk) * VS_AT + nv * 8 + g];
                bf[1] = Vp[(ks * 8 + lk + 4) * VS_AT + nv * 8 + g];
                mma_1688(acc_o[nv], a, bf);
            }
        }
    }

    // ---- epilogue: normalize + tf32-round into g_ao ----
    float invA = 1.0f / row_l0, invB = 1.0f / row_l1;
#pragma unroll
    for (int nv = 0; nv < 8; nv++) {
        int c = h * D_ + nv * 8 + 2 * lk;
        float2 oA = make_float2(to_tf32(acc_o[nv][0] * invA),
                                to_tf32(acc_o[nv][1] * invA));
        float2 oB = make_float2(to_tf32(acc_o[nv][2] * invB),
                                to_tf32(acc_o[nv][3] * invB));
        *(float2*)(g_ao + ((size_t)(b * N_) + n0 + wm + g) * DIM_ + c) = oA;
        *(float2*)(g_ao + ((size_t)(b * N_) + n0 + wm + g + 8) * DIM_ + c) = oB;
    }
}

// ---------------------------------------------------------------------------
// Launch
// ---------------------------------------------------------------------------
extern "C" void kernel_launch(void* const* d_in, const int* in_sizes, int n_in,
                              void* d_out, int out_size) {
    const float* x   = (const float*)d_in[0];
    const float* ctx = (const float*)d_in[1];
    const int*   msk = (const int*)d_in[2];
    const float* Wq  = (const float*)d_in[3];
    const float* bq  = (const float*)d_in[4];
    const float* Wkv = (const float*)d_in[5];
    const float* bkv = (const float*)d_in[6];
    const float* Wp  = (const float*)d_in[7];
    const float* bp  = (const float*)d_in[8];
    float* out = (float*)d_out;

    cudaFuncSetAttribute(attn_mma_kernel,
                         cudaFuncAttributeMaxDynamicSharedMemorySize, SMEM_ATTN);
    cudaFuncSetAttribute(mma_gemm_qkv,
                         cudaFuncAttributeMaxDynamicSharedMemorySize, SMEM_GEMM);
    cudaFuncSetAttribute(mma_gemm_out,
                         cudaFuncAttributeMaxDynamicSharedMemorySize, SMEM_GEMM);

    pack_mask_kernel<<<(B_ * N_) / 8, 256>>>(msk);
    tf32_round_all<<<3145728 / 256, 256>>>(x, ctx, Wq, Wkv, Wp);
    mma_gemm_qkv<<<dim3(24, 32), 256, SMEM_GEMM>>>(bq, bkv);
    attn_mma_kernel<<<dim3(N_ / 128, H_, B_), 256, SMEM_ATTN>>>();
    mma_gemm_out<<<dim3(8, 32), 256, SMEM_GEMM>>>(bp, out);
}